// round 8
// baseline (speedup 1.0000x reference)
#include <cuda_runtime.h>
#include <cuda_bf16.h>
#include <math.h>
#include <cstdint>

// ---------------------------------------------------------------------------
// Problem constants
// ---------------------------------------------------------------------------
namespace {
constexpr int Bb   = 2;
constexpr int Tt   = 2048;
constexpr int Dd   = 768;
constexpr int QKV3 = 3 * Dd;       // 2304
constexpr int Hh   = 12;
constexpr int MROWS = Bb * Tt;     // 4096
constexpr int DFF   = 4 * Dd;      // 3072
constexpr int NDD  = Dd * Dd;      // 589824
constexpr int NW1  = DFF * Dd;     // 2359296
constexpr int CVT_TOTAL = 4 * NDD + 2 * NW1;  // 7077888

// mma.sync GEMM config: CTA tile 128x128, BK=32, 2-stage cp.async pipeline
constexpr int AP   = 40;             // padded row length (bf16 elems), 80B
constexpr int TSZ  = 128 * AP;       // elems per tile (A or B, one of h/l): 5120
constexpr int STG  = 4 * TSZ;        // elems per stage (Ah,Al,Bh,Bl): 20480
constexpr int GSMEM_BYTES = 2 * STG * 2;  // 81920

// attention smem: 2 stages x (Kh,Kl,Vh,Vl) 64x72 bf16 tiles
constexpr int APAD = 72;
constexpr int ATILE = 64 * APAD;        // 4608 elems
constexpr int ASTG  = 4 * ATILE;        // 18432 elems per stage
constexpr int ATTN_SMEM2 = 2 * ASTG * 2;  // 73728 bytes
}

// ---------------------------------------------------------------------------
// Scratch (no allocation allowed)
// ---------------------------------------------------------------------------
__device__ float g_x1 [MROWS * Dd];

__device__ __nv_bfloat16 g_xn_h  [MROWS * Dd],  g_xn_l  [MROWS * Dd];
__device__ __nv_bfloat16 g_qkv_h [MROWS * QKV3], g_qkv_l[MROWS * QKV3];
__device__ __nv_bfloat16 g_ctx_h [MROWS * Dd],  g_ctx_l [MROWS * Dd];
__device__ __nv_bfloat16 g_h_h   [MROWS * DFF], g_h_l   [MROWS * DFF];
__device__ __nv_bfloat16 g_wqkv_h[QKV3 * Dd],   g_wqkv_l[QKV3 * Dd];
__device__ __nv_bfloat16 g_wo_h  [Dd * Dd],     g_wo_l  [Dd * Dd];
__device__ __nv_bfloat16 g_w1_h  [DFF * Dd],    g_w1_l  [DFF * Dd];
__device__ __nv_bfloat16 g_w2_h  [Dd * DFF],    g_w2_l  [Dd * DFF];

// ---------------------------------------------------------------------------
// PTX helpers (baseline PTX, legal at compute_100)
// ---------------------------------------------------------------------------
__device__ __forceinline__ uint32_t smem_u32(const void* p) {
    uint32_t a;
    asm("{ .reg .u64 t; cvta.to.shared.u64 t, %1; cvt.u32.u64 %0, t; }"
        : "=r"(a) : "l"(p));
    return a;
}

__device__ __forceinline__ void cp16(uint32_t dst, const void* src) {
    asm volatile("cp.async.cg.shared.global [%0], [%1], 16;" :: "r"(dst), "l"(src));
}

__device__ __forceinline__ void ldm_x4(uint32_t* r, uint32_t addr) {
    asm volatile("ldmatrix.sync.aligned.m8n8.x4.shared.b16 {%0,%1,%2,%3}, [%4];"
        : "=r"(r[0]), "=r"(r[1]), "=r"(r[2]), "=r"(r[3]) : "r"(addr));
}

__device__ __forceinline__ void ldm_x4_t(uint32_t* r, uint32_t addr) {
    asm volatile("ldmatrix.sync.aligned.m8n8.x4.trans.shared.b16 {%0,%1,%2,%3}, [%4];"
        : "=r"(r[0]), "=r"(r[1]), "=r"(r[2]), "=r"(r[3]) : "r"(addr));
}

__device__ __forceinline__ void mma16816(float* c, const uint32_t* a, const uint32_t* b) {
    asm volatile(
        "mma.sync.aligned.m16n8k16.row.col.f32.bf16.bf16.f32 "
        "{%0,%1,%2,%3}, {%4,%5,%6,%7}, {%8,%9}, {%0,%1,%2,%3};"
        : "+f"(c[0]), "+f"(c[1]), "+f"(c[2]), "+f"(c[3])
        : "r"(a[0]), "r"(a[1]), "r"(a[2]), "r"(a[3]), "r"(b[0]), "r"(b[1]));
}

// pack two floats to bf16x2 (lo = first arg)
__device__ __forceinline__ uint32_t packbf(float lo, float hi) {
    uint32_t r;
    asm("cvt.rn.bf16x2.f32 %0, %1, %2;" : "=r"(r) : "f"(hi), "f"(lo));
    return r;
}

// ---------------------------------------------------------------------------
// LayerNorm -> (hi, lo) bf16 pair
// ---------------------------------------------------------------------------
__global__ __launch_bounds__(256) void ln_hilo(
    const float* __restrict__ x, const float* __restrict__ sc,
    const float* __restrict__ sh,
    __nv_bfloat16* __restrict__ oh, __nv_bfloat16* __restrict__ ol)
{
    const int row = blockIdx.x;
    const float* xr = x + (size_t)row * Dd;
    __shared__ float s1[256], s2[256];
    float a = 0.f, b = 0.f;
    for (int i = threadIdx.x; i < Dd; i += 256) {
        float v = xr[i];
        a += v; b += v * v;
    }
    s1[threadIdx.x] = a; s2[threadIdx.x] = b;
    __syncthreads();
    for (int off = 128; off > 0; off >>= 1) {
        if (threadIdx.x < off) {
            s1[threadIdx.x] += s1[threadIdx.x + off];
            s2[threadIdx.x] += s2[threadIdx.x + off];
        }
        __syncthreads();
    }
    const float mean = s1[0] * (1.f / Dd);
    const float var  = s2[0] * (1.f / Dd) - mean * mean;
    const float rstd = rsqrtf(var + 1e-5f);
    for (int i = threadIdx.x; i < Dd; i += 256) {
        const float v = sc[i] * (xr[i] - mean) * rstd + sh[i];
        const __nv_bfloat16 h = __float2bfloat16(v);
        oh[(size_t)row * Dd + i] = h;
        ol[(size_t)row * Dd + i] = __float2bfloat16(v - __bfloat162float(h));
    }
}

// ---------------------------------------------------------------------------
// All six weight matrices -> (hi, lo) bf16 in ONE launch.
// Regions: [0,3*NDD): wq|wk|wv -> wqkv (contiguous dst), [3NDD,4NDD): wo,
// [4NDD, 4NDD+NW1): w1, [4NDD+NW1, end): w2.
// ---------------------------------------------------------------------------
__global__ __launch_bounds__(256) void cvt_weights(
    const float* __restrict__ wq, const float* __restrict__ wk,
    const float* __restrict__ wv, const float* __restrict__ wo,
    const float* __restrict__ w1, const float* __restrict__ w2,
    __nv_bfloat16* __restrict__ wqkvh, __nv_bfloat16* __restrict__ wqkvl,
    __nv_bfloat16* __restrict__ woh,   __nv_bfloat16* __restrict__ wol,
    __nv_bfloat16* __restrict__ w1h,   __nv_bfloat16* __restrict__ w1l,
    __nv_bfloat16* __restrict__ w2h,   __nv_bfloat16* __restrict__ w2l)
{
    const int gid = blockIdx.x * 256 + threadIdx.x;
    if (gid >= CVT_TOTAL) return;
    float v;
    __nv_bfloat16 *dh, *dl;
    if (gid < 3 * NDD) {
        v = (gid < NDD) ? wq[gid] : (gid < 2 * NDD) ? wk[gid - NDD] : wv[gid - 2 * NDD];
        dh = wqkvh + gid; dl = wqkvl + gid;
    } else if (gid < 4 * NDD) {
        const int j = gid - 3 * NDD;
        v = wo[j]; dh = woh + j; dl = wol + j;
    } else if (gid < 4 * NDD + NW1) {
        const int j = gid - 4 * NDD;
        v = w1[j]; dh = w1h + j; dl = w1l + j;
    } else {
        const int j = gid - 4 * NDD - NW1;
        v = w2[j]; dh = w2h + j; dl = w2l + j;
    }
    const __nv_bfloat16 h = __float2bfloat16(v);
    *dh = h;
    *dl = __float2bfloat16(v - __bfloat162float(h));
}

// ---------------------------------------------------------------------------
// HMMA split-bf16 NT GEMM: C[M,N] = A[M,K] * B[N,K]^T
// A ≈ Ah + Al, B ≈ Bh + Bl; D += AhBh + AhBl + AlBh (fp32 accum)
// EPI: 1 = (hi,lo) bf16 out, no bias; 2 = +bias +res, fp32 out;
//      3 = +bias, GELU, (hi,lo) out
// CTA 128x128, BK=32, 256 thr = 8 warps (2m x 4n), warp tile 64x32
// ---------------------------------------------------------------------------
template<int EPI>
__global__ __launch_bounds__(256) void gemm_mma(
    const __nv_bfloat16* __restrict__ Ah, const __nv_bfloat16* __restrict__ Al,
    const __nv_bfloat16* __restrict__ Bh, const __nv_bfloat16* __restrict__ Bl,
    const float* __restrict__ bias, const float* __restrict__ res,
    float* __restrict__ Cf,
    __nv_bfloat16* __restrict__ Ch, __nv_bfloat16* __restrict__ Cl,
    int M, int N, int K)
{
    extern __shared__ __align__(16) char smem[];
    const uint32_t sb = smem_u32(smem);
    const int tid  = threadIdx.x;
    const int lane = tid & 31;
    const int w    = tid >> 5;
    const int wm   = w & 1;          // 0..1 (m: 64 rows each)
    const int wn   = w >> 1;         // 0..3 (n: 32 cols each)
    const int m0   = blockIdx.y * 128, n0 = blockIdx.x * 128;

    float acc[4][4][4];
    #pragma unroll
    for (int mi = 0; mi < 4; mi++)
        #pragma unroll
        for (int ni = 0; ni < 4; ni++)
            #pragma unroll
            for (int t = 0; t < 4; t++) acc[mi][ni][t] = 0.f;

    const int nc = K >> 5;

    // stage layout (bytes from sb): st*STG*2 + {Ah:0, Al:TSZ*2, Bh:2*TSZ*2, Bl:3*TSZ*2}
    auto load_stage = [&](int st, int c) {
        const int k0 = c << 5;
        const uint32_t stb = sb + (uint32_t)(st * STG * 2);
        #pragma unroll
        for (int i = 0; i < 2; i++) {
            const int id  = tid + i * 256;        // 0..511
            const int row = id >> 2, seg = id & 3;
            const uint32_t d = (uint32_t)((row * AP + seg * 8) * 2);
            const size_t ga = (size_t)(m0 + row) * K + k0 + seg * 8;
            const size_t gb = (size_t)(n0 + row) * K + k0 + seg * 8;
            cp16(stb + d,               Ah + ga);
            cp16(stb + TSZ * 2 + d,     Al + ga);
            cp16(stb + 2 * TSZ * 2 + d, Bh + gb);
            cp16(stb + 3 * TSZ * 2 + d, Bl + gb);
        }
    };

    load_stage(0, 0);
    asm volatile("cp.async.commit_group;");

    for (int c = 0; c < nc; c++) {
        if (c + 1 < nc) load_stage((c + 1) & 1, c + 1);
        asm volatile("cp.async.commit_group;");
        asm volatile("cp.async.wait_group 1;");
        __syncthreads();

        const uint32_t stb = sb + (uint32_t)((c & 1) * STG * 2);
        #pragma unroll
        for (int ks = 0; ks < 2; ks++) {
            // B fragments: 4 n-tiles of 8 (from 2 ldmatrix.x4 pairs)
            uint32_t bh[4][2], bl[4][2];
            #pragma unroll
            for (int np = 0; np < 2; np++) {
                const int row = wn * 32 + np * 16 + ((lane >> 4) & 1) * 8 + (lane & 7);
                const int col = ks * 16 + ((lane >> 3) & 1) * 8;
                const uint32_t off = stb + 2 * TSZ * 2 + (uint32_t)((row * AP + col) * 2);
                uint32_t r[4];
                ldm_x4(r, off);
                bh[np * 2][0] = r[0]; bh[np * 2][1] = r[1];
                bh[np * 2 + 1][0] = r[2]; bh[np * 2 + 1][1] = r[3];
                ldm_x4(r, off + TSZ * 2);
                bl[np * 2][0] = r[0]; bl[np * 2][1] = r[1];
                bl[np * 2 + 1][0] = r[2]; bl[np * 2 + 1][1] = r[3];
            }
            // A fragments per m-tile, immediately consumed
            #pragma unroll
            for (int mi = 0; mi < 4; mi++) {
                const int row = wm * 64 + mi * 16 + (lane & 15);
                const int col = ks * 16 + (lane >> 4) * 8;
                const uint32_t off = stb + (uint32_t)((row * AP + col) * 2);
                uint32_t ah[4], al[4];
                ldm_x4(ah, off);
                ldm_x4(al, off + TSZ * 2);
                #pragma unroll
                for (int ni = 0; ni < 4; ni++) {
                    mma16816(acc[mi][ni], ah, bh[ni]);
                    mma16816(acc[mi][ni], ah, bl[ni]);
                    mma16816(acc[mi][ni], al, bh[ni]);
                }
            }
        }
        __syncthreads();
    }

    // --- epilogue ---
    const int rbase = m0 + wm * 64 + (lane >> 2);
    const int cbase = n0 + wn * 32 + (lane & 3) * 2;
    #pragma unroll
    for (int mi = 0; mi < 4; mi++) {
        #pragma unroll
        for (int ni = 0; ni < 4; ni++) {
            #pragma unroll
            for (int half = 0; half < 2; half++) {
                const int m = rbase + mi * 16 + half * 8;
                const int n = cbase + ni * 8;
                float v0 = acc[mi][ni][half * 2];
                float v1 = acc[mi][ni][half * 2 + 1];
                const size_t o = (size_t)m * N + n;
                if (EPI == 1) {
                    const __nv_bfloat16 h0 = __float2bfloat16(v0);
                    const __nv_bfloat16 h1 = __float2bfloat16(v1);
                    __nv_bfloat162 hp, lp;
                    hp.x = h0; hp.y = h1;
                    lp.x = __float2bfloat16(v0 - __bfloat162float(h0));
                    lp.y = __float2bfloat16(v1 - __bfloat162float(h1));
                    *(__nv_bfloat162*)(Ch + o) = hp;
                    *(__nv_bfloat162*)(Cl + o) = lp;
                } else if (EPI == 2) {
                    const float2 r2 = *(const float2*)(res + o);
                    float2 t = {v0 + bias[n] + r2.x, v1 + bias[n + 1] + r2.y};
                    *(float2*)(Cf + o) = t;
                } else {  // EPI == 3
                    float u0 = v0 + bias[n];
                    float u1 = v1 + bias[n + 1];
                    const float i0 = 0.7978845608028654f * (u0 + 0.044715f * u0 * u0 * u0);
                    const float i1 = 0.7978845608028654f * (u1 + 0.044715f * u1 * u1 * u1);
                    const float g0 = 0.5f * u0 * (1.f + tanhf(i0));
                    const float g1 = 0.5f * u1 * (1.f + tanhf(i1));
                    const __nv_bfloat16 h0 = __float2bfloat16(g0);
                    const __nv_bfloat16 h1 = __float2bfloat16(g1);
                    __nv_bfloat162 hp, lp;
                    hp.x = h0; hp.y = h1;
                    lp.x = __float2bfloat16(g0 - __bfloat162float(h0));
                    lp.y = __float2bfloat16(g1 - __bfloat162float(h1));
                    *(__nv_bfloat162*)(Ch + o) = hp;
                    *(__nv_bfloat162*)(Cl + o) = lp;
                }
            }
        }
    }
}

// ---------------------------------------------------------------------------
// HMMA split-bf16 causal flash attention (unchanged from R7 pass).
// Grid (32, 12, 2), 128 threads.
// ---------------------------------------------------------------------------
__global__ __launch_bounds__(128) void attn_mma(
    const __nv_bfloat16* __restrict__ qkvh, const __nv_bfloat16* __restrict__ qkvl,
    __nv_bfloat16* __restrict__ ch, __nv_bfloat16* __restrict__ cl)
{
    extern __shared__ __align__(16) char smem[];
    const uint32_t sb = smem_u32(smem);
    const int tid = threadIdx.x, lane = tid & 31, w = tid >> 5;
    const int qt = (int)gridDim.x - 1 - (int)blockIdx.x;   // heavy tiles first
    const int h = blockIdx.y, b = blockIdx.z;
    const int wq0 = w * 16;
    const int colb = h * 64;

    // ---- stage Q into stage0 K area, extract fragments ----
    {
        const int rbase = b * Tt + qt * 64;
        #pragma unroll
        for (int i = 0; i < 4; i++) {
            const int t2 = tid + i * 128;
            const int row = t2 >> 3, seg = (t2 & 7) * 8;
            const size_t src = (size_t)(rbase + row) * QKV3 + colb + seg;
            const uint32_t dst = sb + (uint32_t)((row * APAD + seg) * 2);
            cp16(dst,             qkvh + src);
            cp16(dst + ATILE * 2, qkvl + src);
        }
    }
    asm volatile("cp.async.commit_group;");
    asm volatile("cp.async.wait_group 0;");
    __syncthreads();

    uint32_t qh[4][4], ql[4][4];
    #pragma unroll
    for (int ks = 0; ks < 4; ks++) {
        const int row = wq0 + (lane & 15);
        const int col = ks * 16 + (lane >> 4) * 8;
        const uint32_t a = sb + (uint32_t)((row * APAD + col) * 2);
        ldm_x4(qh[ks], a);
        ldm_x4(ql[ks], a + ATILE * 2);
    }
    __syncthreads();

    auto load_kv = [&](int st, int kt) {
        const int rbase = b * Tt + kt * 64;
        #pragma unroll
        for (int i = 0; i < 4; i++) {
            const int t2 = tid + i * 128;
            const int row = t2 >> 3, seg = (t2 & 7) * 8;
            const size_t srcK = (size_t)(rbase + row) * QKV3 + Dd + colb + seg;
            const uint32_t dst = sb + (uint32_t)((st * ASTG + row * APAD + seg) * 2);
            cp16(dst,             qkvh + srcK);        // Kh
            cp16(dst + ATILE * 2, qkvl + srcK);        // Kl
            cp16(dst + ATILE * 4, qkvh + srcK + Dd);   // Vh
            cp16(dst + ATILE * 6, qkvl + srcK + Dd);   // Vl
        }
    };

    float oacc[8][4];
    #pragma unroll
    for (int i = 0; i < 8; i++)
        #pragma unroll
        for (int t = 0; t < 4; t++) oacc[i][t] = 0.f;
    float m0 = -1e30f, m1 = -1e30f, l0 = 0.f, l1 = 0.f;

    load_kv(0, 0);
    asm volatile("cp.async.commit_group;");

    const int r0 = lane >> 2, c0 = (lane & 3) * 2;

    for (int kt = 0; kt <= qt; kt++) {
        if (kt < qt) load_kv((kt + 1) & 1, kt + 1);
        asm volatile("cp.async.commit_group;");
        asm volatile("cp.async.wait_group 1;");
        __syncthreads();
        const uint32_t stb = sb + (uint32_t)((kt & 1) * ASTG * 2);

        // ---- S = Q K^T (split bf16) ----
        float sacc[8][4];
        #pragma unroll
        for (int i = 0; i < 8; i++)
            #pragma unroll
            for (int t = 0; t < 4; t++) sacc[i][t] = 0.f;

        #pragma unroll
        for (int ks = 0; ks < 4; ks++) {
            #pragma unroll
            for (int np = 0; np < 4; np++) {
                const int row = np * 16 + ((lane >> 4) & 1) * 8 + (lane & 7);
                const int col = ks * 16 + ((lane >> 3) & 1) * 8;
                const uint32_t a = stb + (uint32_t)((row * APAD + col) * 2);
                uint32_t rh[4], rl[4];
                ldm_x4(rh, a);
                ldm_x4(rl, a + ATILE * 2);
                uint32_t bh0[2] = {rh[0], rh[1]}, bh1[2] = {rh[2], rh[3]};
                uint32_t bl0[2] = {rl[0], rl[1]}, bl1[2] = {rl[2], rl[3]};
                mma16816(sacc[np * 2],     qh[ks], bh0);
                mma16816(sacc[np * 2],     qh[ks], bl0);
                mma16816(sacc[np * 2],     ql[ks], bh0);
                mma16816(sacc[np * 2 + 1], qh[ks], bh1);
                mma16816(sacc[np * 2 + 1], qh[ks], bl1);
                mma16816(sacc[np * 2 + 1], ql[ks], bh1);
            }
        }

        // ---- scale + causal mask ----
        const bool diag = (kt == qt);
        #pragma unroll
        for (int nt = 0; nt < 8; nt++) {
            #pragma unroll
            for (int e = 0; e < 4; e++) {
                float sv = sacc[nt][e] * 0.125f;
                if (diag) {
                    const int rr = wq0 + r0 + ((e >> 1) << 3);
                    const int cc = nt * 8 + c0 + (e & 1);
                    if (cc > rr) sv = -1e30f;
                }
                sacc[nt][e] = sv;
            }
        }

        // ---- online softmax (row stats via quad shfl) ----
        float mx0 = -1e30f, mx1 = -1e30f;
        #pragma unroll
        for (int nt = 0; nt < 8; nt++) {
            mx0 = fmaxf(mx0, fmaxf(sacc[nt][0], sacc[nt][1]));
            mx1 = fmaxf(mx1, fmaxf(sacc[nt][2], sacc[nt][3]));
        }
        mx0 = fmaxf(mx0, __shfl_xor_sync(0xffffffffu, mx0, 1));
        mx0 = fmaxf(mx0, __shfl_xor_sync(0xffffffffu, mx0, 2));
        mx1 = fmaxf(mx1, __shfl_xor_sync(0xffffffffu, mx1, 1));
        mx1 = fmaxf(mx1, __shfl_xor_sync(0xffffffffu, mx1, 2));
        const float mn0 = fmaxf(m0, mx0), mn1 = fmaxf(m1, mx1);
        const float sc0 = __expf(m0 - mn0), sc1 = __expf(m1 - mn1);
        m0 = mn0; m1 = mn1;

        uint32_t ph[4][4], pl[4][4];
        float s0 = 0.f, s1 = 0.f;
        #pragma unroll
        for (int nt = 0; nt < 8; nt++) {
            const float p0 = __expf(sacc[nt][0] - mn0);
            const float p1 = __expf(sacc[nt][1] - mn0);
            const float p2 = __expf(sacc[nt][2] - mn1);
            const float p3 = __expf(sacc[nt][3] - mn1);
            s0 += p0 + p1; s1 += p2 + p3;
            const float h0 = __bfloat162float(__float2bfloat16(p0));
            const float h1 = __bfloat162float(__float2bfloat16(p1));
            const float h2 = __bfloat162float(__float2bfloat16(p2));
            const float h3 = __bfloat162float(__float2bfloat16(p3));
            const int ks2 = nt >> 1, hf = (nt & 1) * 2;
            ph[ks2][hf]     = packbf(h0, h1);
            ph[ks2][hf + 1] = packbf(h2, h3);
            pl[ks2][hf]     = packbf(p0 - h0, p1 - h1);
            pl[ks2][hf + 1] = packbf(p2 - h2, p3 - h3);
        }
        s0 += __shfl_xor_sync(0xffffffffu, s0, 1);
        s0 += __shfl_xor_sync(0xffffffffu, s0, 2);
        s1 += __shfl_xor_sync(0xffffffffu, s1, 1);
        s1 += __shfl_xor_sync(0xffffffffu, s1, 2);
        l0 = l0 * sc0 + s0;
        l1 = l1 * sc1 + s1;

        #pragma unroll
        for (int dt = 0; dt < 8; dt++) {
            oacc[dt][0] *= sc0; oacc[dt][1] *= sc0;
            oacc[dt][2] *= sc1; oacc[dt][3] *= sc1;
        }

        // ---- O += P V (split bf16, V via trans ldmatrix) ----
        const uint32_t vtb = stb + ATILE * 4;
        #pragma unroll
        for (int ks = 0; ks < 4; ks++) {
            #pragma unroll
            for (int dp = 0; dp < 4; dp++) {
                const int krow = 16 * ks + (lane & 15);
                const int ncol = dp * 16 + (lane >> 4) * 8;
                const uint32_t a = vtb + (uint32_t)((krow * APAD + ncol) * 2);
                uint32_t rh[4], rl[4];
                ldm_x4_t(rh, a);
                ldm_x4_t(rl, a + ATILE * 2);
                uint32_t vh0[2] = {rh[0], rh[1]}, vh1[2] = {rh[2], rh[3]};
                uint32_t vl0[2] = {rl[0], rl[1]}, vl1[2] = {rl[2], rl[3]};
                mma16816(oacc[dp * 2],     ph[ks], vh0);
                mma16816(oacc[dp * 2],     ph[ks], vl0);
                mma16816(oacc[dp * 2],     pl[ks], vh0);
                mma16816(oacc[dp * 2 + 1], ph[ks], vh1);
                mma16816(oacc[dp * 2 + 1], ph[ks], vl1);
                mma16816(oacc[dp * 2 + 1], pl[ks], vh1);
            }
        }
        __syncthreads();
    }

    // ---- epilogue: normalize, write ctx (hi,lo) ----
    const float inv0 = 1.f / l0, inv1 = 1.f / l1;
    const size_t rg0 = (size_t)(b * Tt + qt * 64 + wq0 + r0);
    #pragma unroll
    for (int dt = 0; dt < 8; dt++) {
        const int col = colb + dt * 8 + c0;
        {
            const float v0 = oacc[dt][0] * inv0, v1 = oacc[dt][1] * inv0;
            const __nv_bfloat16 h0 = __float2bfloat16(v0);
            const __nv_bfloat16 h1 = __float2bfloat16(v1);
            __nv_bfloat162 hp, lp;
            hp.x = h0; hp.y = h1;
            lp.x = __float2bfloat16(v0 - __bfloat162float(h0));
            lp.y = __float2bfloat16(v1 - __bfloat162float(h1));
            *(__nv_bfloat162*)(ch + rg0 * Dd + col) = hp;
            *(__nv_bfloat162*)(cl + rg0 * Dd + col) = lp;
        }
        {
            const float v0 = oacc[dt][2] * inv1, v1 = oacc[dt][3] * inv1;
            const __nv_bfloat16 h0 = __float2bfloat16(v0);
            const __nv_bfloat16 h1 = __float2bfloat16(v1);
            __nv_bfloat162 hp, lp;
            hp.x = h0; hp.y = h1;
            lp.x = __float2bfloat16(v0 - __bfloat162float(h0));
            lp.y = __float2bfloat16(v1 - __bfloat162float(h1));
            *(__nv_bfloat162*)(ch + (rg0 + 8) * Dd + col) = hp;
            *(__nv_bfloat162*)(cl + (rg0 + 8) * Dd + col) = lp;
        }
    }
}

// ---------------------------------------------------------------------------
// Launch
// ---------------------------------------------------------------------------
extern "C" void kernel_launch(void* const* d_in, const int* in_sizes, int n_in,
                              void* d_out, int out_size)
{
    const float* x    = (const float*)d_in[0];
    const float* ln1s = (const float*)d_in[1];
    const float* ln1b = (const float*)d_in[2];
    const float* wq   = (const float*)d_in[3];
    const float* wk   = (const float*)d_in[4];
    const float* wv   = (const float*)d_in[5];
    const float* wo   = (const float*)d_in[6];
    const float* bo   = (const float*)d_in[7];
    const float* ln2s = (const float*)d_in[8];
    const float* ln2b = (const float*)d_in[9];
    const float* w1   = (const float*)d_in[10];
    const float* b1   = (const float*)d_in[11];
    const float* w2   = (const float*)d_in[12];
    const float* b2   = (const float*)d_in[13];
    float* out = (float*)d_out;

    float* x1;
    cudaGetSymbolAddress((void**)&x1, g_x1);

    __nv_bfloat16 *xnh, *xnl, *qkvh, *qkvl, *ctxh, *ctxl, *hh, *hl;
    __nv_bfloat16 *wqkvh, *wqkvl, *woh, *wol, *w1h, *w1l, *w2h, *w2l;
    cudaGetSymbolAddress((void**)&xnh,   g_xn_h);
    cudaGetSymbolAddress((void**)&xnl,   g_xn_l);
    cudaGetSymbolAddress((void**)&qkvh,  g_qkv_h);
    cudaGetSymbolAddress((void**)&qkvl,  g_qkv_l);
    cudaGetSymbolAddress((void**)&ctxh,  g_ctx_h);
    cudaGetSymbolAddress((void**)&ctxl,  g_ctx_l);
    cudaGetSymbolAddress((void**)&hh,    g_h_h);
    cudaGetSymbolAddress((void**)&hl,    g_h_l);
    cudaGetSymbolAddress((void**)&wqkvh, g_wqkv_h);
    cudaGetSymbolAddress((void**)&wqkvl, g_wqkv_l);
    cudaGetSymbolAddress((void**)&woh,   g_wo_h);
    cudaGetSymbolAddress((void**)&wol,   g_wo_l);
    cudaGetSymbolAddress((void**)&w1h,   g_w1_h);
    cudaGetSymbolAddress((void**)&w1l,   g_w1_l);
    cudaGetSymbolAddress((void**)&w2h,   g_w2_h);
    cudaGetSymbolAddress((void**)&w2l,   g_w2_l);

    cudaFuncSetAttribute(attn_mma,
                         cudaFuncAttributeMaxDynamicSharedMemorySize, ATTN_SMEM2);
    cudaFuncSetAttribute(gemm_mma<1>,
                         cudaFuncAttributeMaxDynamicSharedMemorySize, GSMEM_BYTES);
    cudaFuncSetAttribute(gemm_mma<2>,
                         cudaFuncAttributeMaxDynamicSharedMemorySize, GSMEM_BYTES);
    cudaFuncSetAttribute(gemm_mma<3>,
                         cudaFuncAttributeMaxDynamicSharedMemorySize, GSMEM_BYTES);

    // All weight conversions in one launch
    cvt_weights<<<(CVT_TOTAL + 255) / 256, 256>>>(
        wq, wk, wv, wo, w1, w2,
        wqkvh, wqkvl, woh, wol, w1h, w1l, w2h, w2l);

    // LN1 -> xn (hi/lo)
    ln_hilo<<<MROWS, 256>>>(x, ln1s, ln1b, xnh, xnl);

    // Fused QKV projection -> qkv (hi/lo bf16), N = 2304
    dim3 gqkv(QKV3 / 128, MROWS / 128);
    gemm_mma<1><<<gqkv, 256, GSMEM_BYTES>>>(xnh, xnl, wqkvh, wqkvl,
                                            nullptr, nullptr, nullptr,
                                            qkvh, qkvl, MROWS, QKV3, Dd);

    // Attention (HMMA flash) -> ctx (hi/lo bf16)
    dim3 ga(Tt / 64, Hh, Bb);
    attn_mma<<<ga, 128, ATTN_SMEM2>>>(qkvh, qkvl, ctxh, ctxl);

    // O projection + bias + residual -> x1 (fp32)
    dim3 gdd(Dd / 128, MROWS / 128);
    gemm_mma<2><<<gdd, 256, GSMEM_BYTES>>>(ctxh, ctxl, woh, wol, bo, x,
                                           x1, nullptr, nullptr, MROWS, Dd, Dd);

    // LN2 -> xn (hi/lo)
    ln_hilo<<<MROWS, 256>>>(x1, ln2s, ln2b, xnh, xnl);

    // MLP1: bias + GELU -> h (hi/lo bf16)
    dim3 g1(DFF / 128, MROWS / 128);
    gemm_mma<3><<<g1, 256, GSMEM_BYTES>>>(xnh, xnl, w1h, w1l, b1, nullptr,
                                          nullptr, hh, hl, MROWS, DFF, Dd);

    // MLP2: bias + residual -> out (fp32)
    gemm_mma<2><<<gdd, 256, GSMEM_BYTES>>>(hh, hl, w2h, w2l, b2, x1,
                                           out, nullptr, nullptr, MROWS, Dd, DFF);
}

// round 10
// speedup vs baseline: 1.1707x; 1.1707x over previous
#include <cuda_runtime.h>
#include <cuda_bf16.h>
#include <math.h>
#include <cstdint>

// ---------------------------------------------------------------------------
// Problem constants
// ---------------------------------------------------------------------------
namespace {
constexpr int Bb   = 2;
constexpr int Tt   = 2048;
constexpr int Dd   = 768;
constexpr int QKV3 = 3 * Dd;       // 2304
constexpr int Hh   = 12;
constexpr int MROWS = Bb * Tt;     // 4096
constexpr int DFF   = 4 * Dd;      // 3072
constexpr int NDD  = Dd * Dd;      // 589824
constexpr int NW1  = DFF * Dd;     // 2359296
constexpr int CVT_TOTAL = 4 * NDD + 2 * NW1;  // 7077888

// mma.sync GEMM config: CTA tile 128x128, BK=32, 2-stage cp.async pipeline
constexpr int AP   = 40;             // padded row length (bf16 elems), 80B
constexpr int TSZ  = 128 * AP;       // elems per tile: 5120
constexpr int STG  = 4 * TSZ;        // elems per stage (Ah,Al,Bh,Bl): 20480
constexpr int GSMEM_BYTES = 2 * STG * 2;  // 81920

// attention smem: 2 stages x (K, V) 64x72 bf16 tiles (single precision)
constexpr int APAD = 72;
constexpr int ATILE = 64 * APAD;        // 4608 elems
constexpr int ASTG  = 2 * ATILE;        // 9216 elems per stage (K, V)
constexpr int ATTN_SMEM2 = 2 * ASTG * 2;  // 36864 bytes
}

// ---------------------------------------------------------------------------
// Scratch (no allocation allowed)
// ---------------------------------------------------------------------------
__device__ float g_x1 [MROWS * Dd];

__device__ __nv_bfloat16 g_xn_h  [MROWS * Dd],  g_xn_l  [MROWS * Dd];
__device__ __nv_bfloat16 g_qkv   [MROWS * QKV3];
__device__ __nv_bfloat16 g_ctx_h [MROWS * Dd],  g_ctx_l [MROWS * Dd];
__device__ __nv_bfloat16 g_h_h   [MROWS * DFF], g_h_l   [MROWS * DFF];
__device__ __nv_bfloat16 g_wqkv_h[QKV3 * Dd],   g_wqkv_l[QKV3 * Dd];
__device__ __nv_bfloat16 g_wo_h  [Dd * Dd],     g_wo_l  [Dd * Dd];
__device__ __nv_bfloat16 g_w1_h  [DFF * Dd],    g_w1_l  [DFF * Dd];
__device__ __nv_bfloat16 g_w2_h  [Dd * DFF],    g_w2_l  [Dd * DFF];

// ---------------------------------------------------------------------------
// PTX helpers (baseline PTX, legal at compute_100)
// ---------------------------------------------------------------------------
__device__ __forceinline__ uint32_t smem_u32(const void* p) {
    uint32_t a;
    asm("{ .reg .u64 t; cvta.to.shared.u64 t, %1; cvt.u32.u64 %0, t; }"
        : "=r"(a) : "l"(p));
    return a;
}

__device__ __forceinline__ void cp16(uint32_t dst, const void* src) {
    asm volatile("cp.async.cg.shared.global [%0], [%1], 16;" :: "r"(dst), "l"(src));
}

__device__ __forceinline__ void ldm_x4(uint32_t* r, uint32_t addr) {
    asm volatile("ldmatrix.sync.aligned.m8n8.x4.shared.b16 {%0,%1,%2,%3}, [%4];"
        : "=r"(r[0]), "=r"(r[1]), "=r"(r[2]), "=r"(r[3]) : "r"(addr));
}

__device__ __forceinline__ void ldm_x4_t(uint32_t* r, uint32_t addr) {
    asm volatile("ldmatrix.sync.aligned.m8n8.x4.trans.shared.b16 {%0,%1,%2,%3}, [%4];"
        : "=r"(r[0]), "=r"(r[1]), "=r"(r[2]), "=r"(r[3]) : "r"(addr));
}

__device__ __forceinline__ void mma16816(float* c, const uint32_t* a, const uint32_t* b) {
    asm volatile(
        "mma.sync.aligned.m16n8k16.row.col.f32.bf16.bf16.f32 "
        "{%0,%1,%2,%3}, {%4,%5,%6,%7}, {%8,%9}, {%0,%1,%2,%3};"
        : "+f"(c[0]), "+f"(c[1]), "+f"(c[2]), "+f"(c[3])
        : "r"(a[0]), "r"(a[1]), "r"(a[2]), "r"(a[3]), "r"(b[0]), "r"(b[1]));
}

// pack two floats to bf16x2 (lo = first arg)
__device__ __forceinline__ uint32_t packbf(float lo, float hi) {
    uint32_t r;
    asm("cvt.rn.bf16x2.f32 %0, %1, %2;" : "=r"(r) : "f"(hi), "f"(lo));
    return r;
}

// ---------------------------------------------------------------------------
// LayerNorm -> (hi, lo) bf16 pair
// ---------------------------------------------------------------------------
__global__ __launch_bounds__(256) void ln_hilo(
    const float* __restrict__ x, const float* __restrict__ sc,
    const float* __restrict__ sh,
    __nv_bfloat16* __restrict__ oh, __nv_bfloat16* __restrict__ ol)
{
    const int row = blockIdx.x;
    const float* xr = x + (size_t)row * Dd;
    __shared__ float s1[256], s2[256];
    float a = 0.f, b = 0.f;
    for (int i = threadIdx.x; i < Dd; i += 256) {
        float v = xr[i];
        a += v; b += v * v;
    }
    s1[threadIdx.x] = a; s2[threadIdx.x] = b;
    __syncthreads();
    for (int off = 128; off > 0; off >>= 1) {
        if (threadIdx.x < off) {
            s1[threadIdx.x] += s1[threadIdx.x + off];
            s2[threadIdx.x] += s2[threadIdx.x + off];
        }
        __syncthreads();
    }
    const float mean = s1[0] * (1.f / Dd);
    const float var  = s2[0] * (1.f / Dd) - mean * mean;
    const float rstd = rsqrtf(var + 1e-5f);
    for (int i = threadIdx.x; i < Dd; i += 256) {
        const float v = sc[i] * (xr[i] - mean) * rstd + sh[i];
        const __nv_bfloat16 h = __float2bfloat16(v);
        oh[(size_t)row * Dd + i] = h;
        ol[(size_t)row * Dd + i] = __float2bfloat16(v - __bfloat162float(h));
    }
}

// ---------------------------------------------------------------------------
// All six weight matrices -> (hi, lo) bf16 in ONE launch.
// ---------------------------------------------------------------------------
__global__ __launch_bounds__(256) void cvt_weights(
    const float* __restrict__ wq, const float* __restrict__ wk,
    const float* __restrict__ wv, const float* __restrict__ wo,
    const float* __restrict__ w1, const float* __restrict__ w2,
    __nv_bfloat16* __restrict__ wqkvh, __nv_bfloat16* __restrict__ wqkvl,
    __nv_bfloat16* __restrict__ woh,   __nv_bfloat16* __restrict__ wol,
    __nv_bfloat16* __restrict__ w1h,   __nv_bfloat16* __restrict__ w1l,
    __nv_bfloat16* __restrict__ w2h,   __nv_bfloat16* __restrict__ w2l)
{
    const int gid = blockIdx.x * 256 + threadIdx.x;
    if (gid >= CVT_TOTAL) return;
    float v;
    __nv_bfloat16 *dh, *dl;
    if (gid < 3 * NDD) {
        v = (gid < NDD) ? wq[gid] : (gid < 2 * NDD) ? wk[gid - NDD] : wv[gid - 2 * NDD];
        dh = wqkvh + gid; dl = wqkvl + gid;
    } else if (gid < 4 * NDD) {
        const int j = gid - 3 * NDD;
        v = wo[j]; dh = woh + j; dl = wol + j;
    } else if (gid < 4 * NDD + NW1) {
        const int j = gid - 4 * NDD;
        v = w1[j]; dh = w1h + j; dl = w1l + j;
    } else {
        const int j = gid - 4 * NDD - NW1;
        v = w2[j]; dh = w2h + j; dl = w2l + j;
    }
    const __nv_bfloat16 h = __float2bfloat16(v);
    *dh = h;
    *dl = __float2bfloat16(v - __bfloat162float(h));
}

// ---------------------------------------------------------------------------
// HMMA split-bf16 NT GEMM: C[M,N] = A[M,K] * B[N,K]^T
// EPI: 1 = single bf16 out, no bias; 2 = +bias +res, fp32 out;
//      3 = +bias, GELU, (hi,lo) out
// CTA 128x128, BK=32, 256 thr = 8 warps (2m x 4n), warp tile 64x32
// ---------------------------------------------------------------------------
template<int EPI>
__global__ __launch_bounds__(256, 2) void gemm_mma(
    const __nv_bfloat16* __restrict__ Ah, const __nv_bfloat16* __restrict__ Al,
    const __nv_bfloat16* __restrict__ Bh, const __nv_bfloat16* __restrict__ Bl,
    const float* __restrict__ bias, const float* __restrict__ res,
    float* __restrict__ Cf,
    __nv_bfloat16* __restrict__ Ch, __nv_bfloat16* __restrict__ Cl,
    int M, int N, int K)
{
    extern __shared__ __align__(16) char smem[];
    const uint32_t sb = smem_u32(smem);
    const int tid  = threadIdx.x;
    const int lane = tid & 31;
    const int w    = tid >> 5;
    const int wm   = w & 1;          // m: 64 rows each
    const int wn   = w >> 1;         // n: 32 cols each
    const int m0   = blockIdx.y * 128, n0 = blockIdx.x * 128;

    float acc[4][4][4];
    #pragma unroll
    for (int mi = 0; mi < 4; mi++)
        #pragma unroll
        for (int ni = 0; ni < 4; ni++)
            #pragma unroll
            for (int t = 0; t < 4; t++) acc[mi][ni][t] = 0.f;

    const int nc = K >> 5;

    auto load_stage = [&](int st, int c) {
        const int k0 = c << 5;
        const uint32_t stb = sb + (uint32_t)(st * STG * 2);
        #pragma unroll
        for (int i = 0; i < 2; i++) {
            const int id  = tid + i * 256;
            const int row = id >> 2, seg = id & 3;
            const uint32_t d = (uint32_t)((row * AP + seg * 8) * 2);
            const size_t ga = (size_t)(m0 + row) * K + k0 + seg * 8;
            const size_t gb = (size_t)(n0 + row) * K + k0 + seg * 8;
            cp16(stb + d,               Ah + ga);
            cp16(stb + TSZ * 2 + d,     Al + ga);
            cp16(stb + 2 * TSZ * 2 + d, Bh + gb);
            cp16(stb + 3 * TSZ * 2 + d, Bl + gb);
        }
    };

    load_stage(0, 0);
    asm volatile("cp.async.commit_group;");

    for (int c = 0; c < nc; c++) {
        if (c + 1 < nc) load_stage((c + 1) & 1, c + 1);
        asm volatile("cp.async.commit_group;");
        asm volatile("cp.async.wait_group 1;");
        __syncthreads();

        const uint32_t stb = sb + (uint32_t)((c & 1) * STG * 2);
        #pragma unroll
        for (int ks = 0; ks < 2; ks++) {
            uint32_t bh[4][2], bl[4][2];
            #pragma unroll
            for (int np = 0; np < 2; np++) {
                const int row = wn * 32 + np * 16 + ((lane >> 4) & 1) * 8 + (lane & 7);
                const int col = ks * 16 + ((lane >> 3) & 1) * 8;
                const uint32_t off = stb + 2 * TSZ * 2 + (uint32_t)((row * AP + col) * 2);
                uint32_t r[4];
                ldm_x4(r, off);
                bh[np * 2][0] = r[0]; bh[np * 2][1] = r[1];
                bh[np * 2 + 1][0] = r[2]; bh[np * 2 + 1][1] = r[3];
                ldm_x4(r, off + TSZ * 2);
                bl[np * 2][0] = r[0]; bl[np * 2][1] = r[1];
                bl[np * 2 + 1][0] = r[2]; bl[np * 2 + 1][1] = r[3];
            }
            #pragma unroll
            for (int mi = 0; mi < 4; mi++) {
                const int row = wm * 64 + mi * 16 + (lane & 15);
                const int col = ks * 16 + (lane >> 4) * 8;
                const uint32_t off = stb + (uint32_t)((row * AP + col) * 2);
                uint32_t ah[4], al[4];
                ldm_x4(ah, off);
                ldm_x4(al, off + TSZ * 2);
                #pragma unroll
                for (int ni = 0; ni < 4; ni++) {
                    mma16816(acc[mi][ni], ah, bh[ni]);
                    mma16816(acc[mi][ni], ah, bl[ni]);
                    mma16816(acc[mi][ni], al, bh[ni]);
                }
            }
        }
        __syncthreads();
    }

    // --- epilogue ---
    const int rbase = m0 + wm * 64 + (lane >> 2);
    const int cbase = n0 + wn * 32 + (lane & 3) * 2;
    #pragma unroll
    for (int mi = 0; mi < 4; mi++) {
        #pragma unroll
        for (int ni = 0; ni < 4; ni++) {
            #pragma unroll
            for (int half = 0; half < 2; half++) {
                const int m = rbase + mi * 16 + half * 8;
                const int n = cbase + ni * 8;
                float v0 = acc[mi][ni][half * 2];
                float v1 = acc[mi][ni][half * 2 + 1];
                const size_t o = (size_t)m * N + n;
                if (EPI == 1) {
                    __nv_bfloat162 hp;
                    hp.x = __float2bfloat16(v0);
                    hp.y = __float2bfloat16(v1);
                    *(__nv_bfloat162*)(Ch + o) = hp;
                } else if (EPI == 2) {
                    const float2 r2 = *(const float2*)(res + o);
                    float2 t = {v0 + bias[n] + r2.x, v1 + bias[n + 1] + r2.y};
                    *(float2*)(Cf + o) = t;
                } else {  // EPI == 3
                    float u0 = v0 + bias[n];
                    float u1 = v1 + bias[n + 1];
                    const float i0 = 0.7978845608028654f * (u0 + 0.044715f * u0 * u0 * u0);
                    const float i1 = 0.7978845608028654f * (u1 + 0.044715f * u1 * u1 * u1);
                    const float g0 = 0.5f * u0 * (1.f + tanhf(i0));
                    const float g1 = 0.5f * u1 * (1.f + tanhf(i1));
                    const __nv_bfloat16 h0 = __float2bfloat16(g0);
                    const __nv_bfloat16 h1 = __float2bfloat16(g1);
                    __nv_bfloat162 hp, lp;
                    hp.x = h0; hp.y = h1;
                    lp.x = __float2bfloat16(g0 - __bfloat162float(h0));
                    lp.y = __float2bfloat16(g1 - __bfloat162float(h1));
                    *(__nv_bfloat162*)(Ch + o) = hp;
                    *(__nv_bfloat162*)(Cl + o) = lp;
                }
            }
        }
    }
}

// ---------------------------------------------------------------------------
// HMMA causal flash attention, single-bf16 Q/K/V, split P.
// Grid (32, 12, 2), 128 threads, forced 4 CTAs/SM.
// ---------------------------------------------------------------------------
__global__ __launch_bounds__(128, 4) void attn_mma(
    const __nv_bfloat16* __restrict__ qkv,
    __nv_bfloat16* __restrict__ ch, __nv_bfloat16* __restrict__ cl)
{
    extern __shared__ __align__(16) char smem[];
    const uint32_t sb = smem_u32(smem);
    const int tid = threadIdx.x, lane = tid & 31, w = tid >> 5;
    const int qt = (int)gridDim.x - 1 - (int)blockIdx.x;   // heavy tiles first
    const int h = blockIdx.y, b = blockIdx.z;
    const int wq0 = w * 16;
    const int colb = h * 64;

    // ---- stage Q into stage0 K area, extract fragments ----
    {
        const int rbase = b * Tt + qt * 64;
        #pragma unroll
        for (int i = 0; i < 4; i++) {
            const int t2 = tid + i * 128;
            const int row = t2 >> 3, seg = (t2 & 7) * 8;
            const size_t src = (size_t)(rbase + row) * QKV3 + colb + seg;
            cp16(sb + (uint32_t)((row * APAD + seg) * 2), qkv + src);
        }
    }
    asm volatile("cp.async.commit_group;");
    asm volatile("cp.async.wait_group 0;");
    __syncthreads();

    uint32_t qh[4][4];
    #pragma unroll
    for (int ks = 0; ks < 4; ks++) {
        const int row = wq0 + (lane & 15);
        const int col = ks * 16 + (lane >> 4) * 8;
        ldm_x4(qh[ks], sb + (uint32_t)((row * APAD + col) * 2));
    }
    __syncthreads();

    auto load_kv = [&](int st, int kt) {
        const int rbase = b * Tt + kt * 64;
        #pragma unroll
        for (int i = 0; i < 4; i++) {
            const int t2 = tid + i * 128;
            const int row = t2 >> 3, seg = (t2 & 7) * 8;
            const size_t srcK = (size_t)(rbase + row) * QKV3 + Dd + colb + seg;
            const uint32_t dst = sb + (uint32_t)((st * ASTG + row * APAD + seg) * 2);
            cp16(dst,             qkv + srcK);        // K
            cp16(dst + ATILE * 2, qkv + srcK + Dd);   // V
        }
    };

    float oacc[8][4];
    #pragma unroll
    for (int i = 0; i < 8; i++)
        #pragma unroll
        for (int t = 0; t < 4; t++) oacc[i][t] = 0.f;
    float m0 = -1e30f, m1 = -1e30f, l0 = 0.f, l1 = 0.f;

    load_kv(0, 0);
    asm volatile("cp.async.commit_group;");

    const int r0 = lane >> 2, c0 = (lane & 3) * 2;

    for (int kt = 0; kt <= qt; kt++) {
        if (kt < qt) load_kv((kt + 1) & 1, kt + 1);
        asm volatile("cp.async.commit_group;");
        asm volatile("cp.async.wait_group 1;");
        __syncthreads();
        const uint32_t stb = sb + (uint32_t)((kt & 1) * ASTG * 2);

        // ---- S = Q K^T ----
        float sacc[8][4];
        #pragma unroll
        for (int i = 0; i < 8; i++)
            #pragma unroll
            for (int t = 0; t < 4; t++) sacc[i][t] = 0.f;

        #pragma unroll
        for (int ks = 0; ks < 4; ks++) {
            #pragma unroll
            for (int np = 0; np < 4; np++) {
                const int row = np * 16 + ((lane >> 4) & 1) * 8 + (lane & 7);
                const int col = ks * 16 + ((lane >> 3) & 1) * 8;
                uint32_t rk[4];
                ldm_x4(rk, stb + (uint32_t)((row * APAD + col) * 2));
                uint32_t b0[2] = {rk[0], rk[1]}, b1[2] = {rk[2], rk[3]};
                mma16816(sacc[np * 2],     qh[ks], b0);
                mma16816(sacc[np * 2 + 1], qh[ks], b1);
            }
        }

        // ---- scale + causal mask ----
        const bool diag = (kt == qt);
        #pragma unroll
        for (int nt = 0; nt < 8; nt++) {
            #pragma unroll
            for (int e = 0; e < 4; e++) {
                float sv = sacc[nt][e] * 0.125f;
                if (diag) {
                    const int rr = wq0 + r0 + ((e >> 1) << 3);
                    const int cc = nt * 8 + c0 + (e & 1);
                    if (cc > rr) sv = -1e30f;
                }
                sacc[nt][e] = sv;
            }
        }

        // ---- online softmax (row stats via quad shfl) ----
        float mx0 = -1e30f, mx1 = -1e30f;
        #pragma unroll
        for (int nt = 0; nt < 8; nt++) {
            mx0 = fmaxf(mx0, fmaxf(sacc[nt][0], sacc[nt][1]));
            mx1 = fmaxf(mx1, fmaxf(sacc[nt][2], sacc[nt][3]));
        }
        mx0 = fmaxf(mx0, __shfl_xor_sync(0xffffffffu, mx0, 1));
        mx0 = fmaxf(mx0, __shfl_xor_sync(0xffffffffu, mx0, 2));
        mx1 = fmaxf(mx1, __shfl_xor_sync(0xffffffffu, mx1, 1));
        mx1 = fmaxf(mx1, __shfl_xor_sync(0xffffffffu, mx1, 2));
        const float mn0 = fmaxf(m0, mx0), mn1 = fmaxf(m1, mx1);
        const float sc0 = __expf(m0 - mn0), sc1 = __expf(m1 - mn1);
        m0 = mn0; m1 = mn1;

        uint32_t ph[4][4], pl[4][4];
        float s0 = 0.f, s1 = 0.f;
        #pragma unroll
        for (int nt = 0; nt < 8; nt++) {
            const float p0 = __expf(sacc[nt][0] - mn0);
            const float p1 = __expf(sacc[nt][1] - mn0);
            const float p2 = __expf(sacc[nt][2] - mn1);
            const float p3 = __expf(sacc[nt][3] - mn1);
            s0 += p0 + p1; s1 += p2 + p3;
            const float h0 = __bfloat162float(__float2bfloat16(p0));
            const float h1 = __bfloat162float(__float2bfloat16(p1));
            const float h2 = __bfloat162float(__float2bfloat16(p2));
            const float h3 = __bfloat162float(__float2bfloat16(p3));
            const int ks2 = nt >> 1, hf = (nt & 1) * 2;
            ph[ks2][hf]     = packbf(h0, h1);
            ph[ks2][hf + 1] = packbf(h2, h3);
            pl[ks2][hf]     = packbf(p0 - h0, p1 - h1);
            pl[ks2][hf + 1] = packbf(p2 - h2, p3 - h3);
        }
        s0 += __shfl_xor_sync(0xffffffffu, s0, 1);
        s0 += __shfl_xor_sync(0xffffffffu, s0, 2);
        s1 += __shfl_xor_sync(0xffffffffu, s1, 1);
        s1 += __shfl_xor_sync(0xffffffffu, s1, 2);
        l0 = l0 * sc0 + s0;
        l1 = l1 * sc1 + s1;

        #pragma unroll
        for (int dt = 0; dt < 8; dt++) {
            oacc[dt][0] *= sc0; oacc[dt][1] *= sc0;
            oacc[dt][2] *= sc1; oacc[dt][3] *= sc1;
        }

        // ---- O += (Ph + Pl) V (V via trans ldmatrix) ----
        const uint32_t vtb = stb + ATILE * 2;
        #pragma unroll
        for (int ks = 0; ks < 4; ks++) {
            #pragma unroll
            for (int dp = 0; dp < 4; dp++) {
                const int krow = 16 * ks + (lane & 15);
                const int ncol = dp * 16 + (lane >> 4) * 8;
                uint32_t rv[4];
                ldm_x4_t(rv, vtb + (uint32_t)((krow * APAD + ncol) * 2));
                uint32_t v0[2] = {rv[0], rv[1]}, v1[2] = {rv[2], rv[3]};
                mma16816(oacc[dp * 2],     ph[ks], v0);
                mma16816(oacc[dp * 2],     pl[ks], v0);
                mma16816(oacc[dp * 2 + 1], ph[ks], v1);
                mma16816(oacc[dp * 2 + 1], pl[ks], v1);
            }
        }
        __syncthreads();
    }

    // ---- epilogue: normalize, write ctx (hi,lo) ----
    const float inv0 = 1.f / l0, inv1 = 1.f / l1;
    const size_t rg0 = (size_t)(b * Tt + qt * 64 + wq0 + r0);
    #pragma unroll
    for (int dt = 0; dt < 8; dt++) {
        const int col = colb + dt * 8 + c0;
        {
            const float v0 = oacc[dt][0] * inv0, v1 = oacc[dt][1] * inv0;
            const __nv_bfloat16 h0 = __float2bfloat16(v0);
            const __nv_bfloat16 h1 = __float2bfloat16(v1);
            __nv_bfloat162 hp, lp;
            hp.x = h0; hp.y = h1;
            lp.x = __float2bfloat16(v0 - __bfloat162float(h0));
            lp.y = __float2bfloat16(v1 - __bfloat162float(h1));
            *(__nv_bfloat162*)(ch + rg0 * Dd + col) = hp;
            *(__nv_bfloat162*)(cl + rg0 * Dd + col) = lp;
        }
        {
            const float v0 = oacc[dt][2] * inv1, v1 = oacc[dt][3] * inv1;
            const __nv_bfloat16 h0 = __float2bfloat16(v0);
            const __nv_bfloat16 h1 = __float2bfloat16(v1);
            __nv_bfloat162 hp, lp;
            hp.x = h0; hp.y = h1;
            lp.x = __float2bfloat16(v0 - __bfloat162float(h0));
            lp.y = __float2bfloat16(v1 - __bfloat162float(h1));
            *(__nv_bfloat162*)(ch + (rg0 + 8) * Dd + col) = hp;
            *(__nv_bfloat162*)(cl + (rg0 + 8) * Dd + col) = lp;
        }
    }
}

// ---------------------------------------------------------------------------
// Launch
// ---------------------------------------------------------------------------
extern "C" void kernel_launch(void* const* d_in, const int* in_sizes, int n_in,
                              void* d_out, int out_size)
{
    const float* x    = (const float*)d_in[0];
    const float* ln1s = (const float*)d_in[1];
    const float* ln1b = (const float*)d_in[2];
    const float* wq   = (const float*)d_in[3];
    const float* wk   = (const float*)d_in[4];
    const float* wv   = (const float*)d_in[5];
    const float* wo   = (const float*)d_in[6];
    const float* bo   = (const float*)d_in[7];
    const float* ln2s = (const float*)d_in[8];
    const float* ln2b = (const float*)d_in[9];
    const float* w1   = (const float*)d_in[10];
    const float* b1   = (const float*)d_in[11];
    const float* w2   = (const float*)d_in[12];
    const float* b2   = (const float*)d_in[13];
    float* out = (float*)d_out;

    float* x1;
    cudaGetSymbolAddress((void**)&x1, g_x1);

    __nv_bfloat16 *xnh, *xnl, *qkv, *ctxh, *ctxl, *hh, *hl;
    __nv_bfloat16 *wqkvh, *wqkvl, *woh, *wol, *w1h, *w1l, *w2h, *w2l;
    cudaGetSymbolAddress((void**)&xnh,   g_xn_h);
    cudaGetSymbolAddress((void**)&xnl,   g_xn_l);
    cudaGetSymbolAddress((void**)&qkv,   g_qkv);
    cudaGetSymbolAddress((void**)&ctxh,  g_ctx_h);
    cudaGetSymbolAddress((void**)&ctxl,  g_ctx_l);
    cudaGetSymbolAddress((void**)&hh,    g_h_h);
    cudaGetSymbolAddress((void**)&hl,    g_h_l);
    cudaGetSymbolAddress((void**)&wqkvh, g_wqkv_h);
    cudaGetSymbolAddress((void**)&wqkvl, g_wqkv_l);
    cudaGetSymbolAddress((void**)&woh,   g_wo_h);
    cudaGetSymbolAddress((void**)&wol,   g_wo_l);
    cudaGetSymbolAddress((void**)&w1h,   g_w1_h);
    cudaGetSymbolAddress((void**)&w1l,   g_w1_l);
    cudaGetSymbolAddress((void**)&w2h,   g_w2_h);
    cudaGetSymbolAddress((void**)&w2l,   g_w2_l);

    cudaFuncSetAttribute(attn_mma,
                         cudaFuncAttributeMaxDynamicSharedMemorySize, ATTN_SMEM2);
    cudaFuncSetAttribute(gemm_mma<1>,
                         cudaFuncAttributeMaxDynamicSharedMemorySize, GSMEM_BYTES);
    cudaFuncSetAttribute(gemm_mma<2>,
                         cudaFuncAttributeMaxDynamicSharedMemorySize, GSMEM_BYTES);
    cudaFuncSetAttribute(gemm_mma<3>,
                         cudaFuncAttributeMaxDynamicSharedMemorySize, GSMEM_BYTES);

    // All weight conversions in one launch
    cvt_weights<<<(CVT_TOTAL + 255) / 256, 256>>>(
        wq, wk, wv, wo, w1, w2,
        wqkvh, wqkvl, woh, wol, w1h, w1l, w2h, w2l);

    // LN1 -> xn (hi/lo)
    ln_hilo<<<MROWS, 256>>>(x, ln1s, ln1b, xnh, xnl);

    // Fused QKV projection -> qkv (single bf16), N = 2304
    dim3 gqkv(QKV3 / 128, MROWS / 128);
    gemm_mma<1><<<gqkv, 256, GSMEM_BYTES>>>(xnh, xnl, wqkvh, wqkvl,
                                            nullptr, nullptr, nullptr,
                                            qkv, nullptr, MROWS, QKV3, Dd);

    // Attention (HMMA flash) -> ctx (hi/lo bf16)
    dim3 ga(Tt / 64, Hh, Bb);
    attn_mma<<<ga, 128, ATTN_SMEM2>>>(qkv, ctxh, ctxl);

    // O projection + bias + residual -> x1 (fp32)
    dim3 gdd(Dd / 128, MROWS / 128);
    gemm_mma<2><<<gdd, 256, GSMEM_BYTES>>>(ctxh, ctxl, woh, wol, bo, x,
                                           x1, nullptr, nullptr, MROWS, Dd, Dd);

    // LN2 -> xn (hi/lo)
    ln_hilo<<<MROWS, 256>>>(x1, ln2s, ln2b, xnh, xnl);

    // MLP1: bias + GELU -> h (hi/lo bf16)
    dim3 g1(DFF / 128, MROWS / 128);
    gemm_mma<3><<<g1, 256, GSMEM_BYTES>>>(xnh, xnl, w1h, w1l, b1, nullptr,
                                          nullptr, hh, hl, MROWS, DFF, Dd);

    // MLP2: bias + residual -> out (fp32)
    gemm_mma<2><<<gdd, 256, GSMEM_BYTES>>>(hh, hl, w2h, w2l, b2, x1,
                                           out, nullptr, nullptr, MROWS, Dd, DFF);
}

// round 12
// speedup vs baseline: 1.2791x; 1.0926x over previous
#include <cuda_runtime.h>
#include <cuda_bf16.h>
#include <math.h>
#include <cstdint>

// ---------------------------------------------------------------------------
// Problem constants
// ---------------------------------------------------------------------------
namespace {
constexpr int Bb   = 2;
constexpr int Tt   = 2048;
constexpr int Dd   = 768;
constexpr int QKV3 = 3 * Dd;       // 2304
constexpr int Hh   = 12;
constexpr int MROWS = Bb * Tt;     // 4096
constexpr int DFF   = 4 * Dd;      // 3072
constexpr int NDD  = Dd * Dd;      // 589824
constexpr int NW1  = DFF * Dd;     // 2359296
constexpr int CVT_TOTAL = 4 * NDD + 2 * NW1;  // 7077888

// split GEMM config: CTA tile 128x128, BK=32, 2-stage cp.async pipeline
constexpr int AP   = 40;             // padded row length (bf16 elems), 80B
constexpr int TSZ  = 128 * AP;       // elems per tile: 5120
constexpr int STG  = 4 * TSZ;        // per stage (Ah,Al,Bh,Bl): 20480
constexpr int GSMEM_BYTES = 2 * STG * 2;  // 81920

// plain GEMM: per stage (A,B) only
constexpr int PSTG = 2 * TSZ;        // 10240
constexpr int PSMEM_BYTES = 2 * PSTG * 2;  // 40960

// attention smem: 2 stages x (K, V) 64x72 bf16 tiles
constexpr int APAD = 72;
constexpr int ATILE = 64 * APAD;        // 4608 elems
constexpr int ASTG  = 2 * ATILE;        // 9216 elems per stage
constexpr int ATTN_SMEM2 = 2 * ASTG * 2;  // 36864 bytes
}

// ---------------------------------------------------------------------------
// Scratch (no allocation allowed)
// ---------------------------------------------------------------------------
__device__ float g_x1 [MROWS * Dd];

__device__ __nv_bfloat16 g_xn_h  [MROWS * Dd],  g_xn_l  [MROWS * Dd];
__device__ __nv_bfloat16 g_qkv   [MROWS * QKV3];
__device__ __nv_bfloat16 g_ctx_h [MROWS * Dd],  g_ctx_l [MROWS * Dd];
__device__ __nv_bfloat16 g_h_h   [MROWS * DFF], g_h_l   [MROWS * DFF];
__device__ __nv_bfloat16 g_wqkv_h[QKV3 * Dd],   g_wqkv_l[QKV3 * Dd];
__device__ __nv_bfloat16 g_wo_h  [Dd * Dd],     g_wo_l  [Dd * Dd];
__device__ __nv_bfloat16 g_w1_h  [DFF * Dd],    g_w1_l  [DFF * Dd];
__device__ __nv_bfloat16 g_w2_h  [Dd * DFF],    g_w2_l  [Dd * DFF];

// ---------------------------------------------------------------------------
// PTX helpers (baseline PTX, legal at compute_100)
// ---------------------------------------------------------------------------
__device__ __forceinline__ uint32_t smem_u32(const void* p) {
    uint32_t a;
    asm("{ .reg .u64 t; cvta.to.shared.u64 t, %1; cvt.u32.u64 %0, t; }"
        : "=r"(a) : "l"(p));
    return a;
}

__device__ __forceinline__ void cp16(uint32_t dst, const void* src) {
    asm volatile("cp.async.cg.shared.global [%0], [%1], 16;" :: "r"(dst), "l"(src));
}

__device__ __forceinline__ void ldm_x4(uint32_t* r, uint32_t addr) {
    asm volatile("ldmatrix.sync.aligned.m8n8.x4.shared.b16 {%0,%1,%2,%3}, [%4];"
        : "=r"(r[0]), "=r"(r[1]), "=r"(r[2]), "=r"(r[3]) : "r"(addr));
}

__device__ __forceinline__ void ldm_x4_t(uint32_t* r, uint32_t addr) {
    asm volatile("ldmatrix.sync.aligned.m8n8.x4.trans.shared.b16 {%0,%1,%2,%3}, [%4];"
        : "=r"(r[0]), "=r"(r[1]), "=r"(r[2]), "=r"(r[3]) : "r"(addr));
}

__device__ __forceinline__ void mma16816(float* c, const uint32_t* a, const uint32_t* b) {
    asm volatile(
        "mma.sync.aligned.m16n8k16.row.col.f32.bf16.bf16.f32 "
        "{%0,%1,%2,%3}, {%4,%5,%6,%7}, {%8,%9}, {%0,%1,%2,%3};"
        : "+f"(c[0]), "+f"(c[1]), "+f"(c[2]), "+f"(c[3])
        : "r"(a[0]), "r"(a[1]), "r"(a[2]), "r"(a[3]), "r"(b[0]), "r"(b[1]));
}

// pack two floats to bf16x2 (lo = first arg)
__device__ __forceinline__ uint32_t packbf(float lo, float hi) {
    uint32_t r;
    asm("cvt.rn.bf16x2.f32 %0, %1, %2;" : "=r"(r) : "f"(hi), "f"(lo));
    return r;
}

// ---------------------------------------------------------------------------
// LayerNorm -> (hi, lo) bf16 pair
// ---------------------------------------------------------------------------
__global__ __launch_bounds__(256) void ln_hilo(
    const float* __restrict__ x, const float* __restrict__ sc,
    const float* __restrict__ sh,
    __nv_bfloat16* __restrict__ oh, __nv_bfloat16* __restrict__ ol)
{
    const int row = blockIdx.x;
    const float* xr = x + (size_t)row * Dd;
    __shared__ float s1[256], s2[256];
    float a = 0.f, b = 0.f;
    for (int i = threadIdx.x; i < Dd; i += 256) {
        float v = xr[i];
        a += v; b += v * v;
    }
    s1[threadIdx.x] = a; s2[threadIdx.x] = b;
    __syncthreads();
    for (int off = 128; off > 0; off >>= 1) {
        if (threadIdx.x < off) {
            s1[threadIdx.x] += s1[threadIdx.x + off];
            s2[threadIdx.x] += s2[threadIdx.x + off];
        }
        __syncthreads();
    }
    const float mean = s1[0] * (1.f / Dd);
    const float var  = s2[0] * (1.f / Dd) - mean * mean;
    const float rstd = rsqrtf(var + 1e-5f);
    for (int i = threadIdx.x; i < Dd; i += 256) {
        const float v = sc[i] * (xr[i] - mean) * rstd + sh[i];
        const __nv_bfloat16 h = __float2bfloat16(v);
        oh[(size_t)row * Dd + i] = h;
        ol[(size_t)row * Dd + i] = __float2bfloat16(v - __bfloat162float(h));
    }
}

// ---------------------------------------------------------------------------
// All six weight matrices -> (hi, lo) bf16 in ONE launch.
// ---------------------------------------------------------------------------
__global__ __launch_bounds__(256) void cvt_weights(
    const float* __restrict__ wq, const float* __restrict__ wk,
    const float* __restrict__ wv, const float* __restrict__ wo,
    const float* __restrict__ w1, const float* __restrict__ w2,
    __nv_bfloat16* __restrict__ wqkvh, __nv_bfloat16* __restrict__ wqkvl,
    __nv_bfloat16* __restrict__ woh,   __nv_bfloat16* __restrict__ wol,
    __nv_bfloat16* __restrict__ w1h,   __nv_bfloat16* __restrict__ w1l,
    __nv_bfloat16* __restrict__ w2h,   __nv_bfloat16* __restrict__ w2l)
{
    const int gid = blockIdx.x * 256 + threadIdx.x;
    if (gid >= CVT_TOTAL) return;
    float v;
    __nv_bfloat16 *dh, *dl;
    if (gid < 3 * NDD) {
        v = (gid < NDD) ? wq[gid] : (gid < 2 * NDD) ? wk[gid - NDD] : wv[gid - 2 * NDD];
        dh = wqkvh + gid; dl = wqkvl + gid;
    } else if (gid < 4 * NDD) {
        const int j = gid - 3 * NDD;
        v = wo[j]; dh = woh + j; dl = wol + j;
    } else if (gid < 4 * NDD + NW1) {
        const int j = gid - 4 * NDD;
        v = w1[j]; dh = w1h + j; dl = w1l + j;
    } else {
        const int j = gid - 4 * NDD - NW1;
        v = w2[j]; dh = w2h + j; dl = w2l + j;
    }
    const __nv_bfloat16 h = __float2bfloat16(v);
    *dh = h;
    *dl = __float2bfloat16(v - __bfloat162float(h));
}

// ---------------------------------------------------------------------------
// PLAIN bf16 NT GEMM: C = A * B^T, single bf16 out (QKV projection).
// CTA 128x128, BK=32, 256 thr = 8 warps (2m x 4n), warp tile 64x32.
// ---------------------------------------------------------------------------
__global__ __launch_bounds__(256, 2) void gemm_plain(
    const __nv_bfloat16* __restrict__ A, const __nv_bfloat16* __restrict__ B,
    __nv_bfloat16* __restrict__ C, int M, int N, int K)
{
    extern __shared__ __align__(16) char smem[];
    const uint32_t sb = smem_u32(smem);
    const int tid  = threadIdx.x;
    const int lane = tid & 31;
    const int w    = tid >> 5;
    const int wm   = w & 1;
    const int wn   = w >> 1;
    const int m0   = blockIdx.y * 128, n0 = blockIdx.x * 128;

    float acc[4][4][4];
    #pragma unroll
    for (int mi = 0; mi < 4; mi++)
        #pragma unroll
        for (int ni = 0; ni < 4; ni++)
            #pragma unroll
            for (int t = 0; t < 4; t++) acc[mi][ni][t] = 0.f;

    const int nc = K >> 5;

    auto load_stage = [&](int st, int c) {
        const int k0 = c << 5;
        const uint32_t stb = sb + (uint32_t)(st * PSTG * 2);
        #pragma unroll
        for (int i = 0; i < 2; i++) {
            const int id  = tid + i * 256;
            const int row = id >> 2, seg = id & 3;
            const uint32_t d = (uint32_t)((row * AP + seg * 8) * 2);
            cp16(stb + d,           A + (size_t)(m0 + row) * K + k0 + seg * 8);
            cp16(stb + TSZ * 2 + d, B + (size_t)(n0 + row) * K + k0 + seg * 8);
        }
    };

    load_stage(0, 0);
    asm volatile("cp.async.commit_group;");

    for (int c = 0; c < nc; c++) {
        if (c + 1 < nc) load_stage((c + 1) & 1, c + 1);
        asm volatile("cp.async.commit_group;");
        asm volatile("cp.async.wait_group 1;");
        __syncthreads();

        const uint32_t stb = sb + (uint32_t)((c & 1) * PSTG * 2);
        #pragma unroll
        for (int ks = 0; ks < 2; ks++) {
            uint32_t bb[4][2];
            #pragma unroll
            for (int np = 0; np < 2; np++) {
                const int row = wn * 32 + np * 16 + ((lane >> 4) & 1) * 8 + (lane & 7);
                const int col = ks * 16 + ((lane >> 3) & 1) * 8;
                uint32_t r[4];
                ldm_x4(r, stb + TSZ * 2 + (uint32_t)((row * AP + col) * 2));
                bb[np * 2][0] = r[0]; bb[np * 2][1] = r[1];
                bb[np * 2 + 1][0] = r[2]; bb[np * 2 + 1][1] = r[3];
            }
            #pragma unroll
            for (int mi = 0; mi < 4; mi++) {
                const int row = wm * 64 + mi * 16 + (lane & 15);
                const int col = ks * 16 + (lane >> 4) * 8;
                uint32_t aa[4];
                ldm_x4(aa, stb + (uint32_t)((row * AP + col) * 2));
                #pragma unroll
                for (int ni = 0; ni < 4; ni++)
                    mma16816(acc[mi][ni], aa, bb[ni]);
            }
        }
        __syncthreads();
    }

    const int rbase = m0 + wm * 64 + (lane >> 2);
    const int cbase = n0 + wn * 32 + (lane & 3) * 2;
    #pragma unroll
    for (int mi = 0; mi < 4; mi++)
        #pragma unroll
        for (int ni = 0; ni < 4; ni++)
            #pragma unroll
            for (int half = 0; half < 2; half++) {
                const int m = rbase + mi * 16 + half * 8;
                const int n = cbase + ni * 8;
                __nv_bfloat162 hp;
                hp.x = __float2bfloat16(acc[mi][ni][half * 2]);
                hp.y = __float2bfloat16(acc[mi][ni][half * 2 + 1]);
                *(__nv_bfloat162*)(C + (size_t)m * N + n) = hp;
            }
}

// ---------------------------------------------------------------------------
// HMMA split-bf16 NT GEMM: C[M,N] = A[M,K] * B[N,K]^T
// EPI: 2 = +bias +res, fp32 out; 3 = +bias, GELU, (hi,lo) out
// CTA 128x128, BK=32, 256 thr = 8 warps (2m x 4n), warp tile 64x32
// ---------------------------------------------------------------------------
template<int EPI>
__global__ __launch_bounds__(256, 2) void gemm_mma(
    const __nv_bfloat16* __restrict__ Ah, const __nv_bfloat16* __restrict__ Al,
    const __nv_bfloat16* __restrict__ Bh, const __nv_bfloat16* __restrict__ Bl,
    const float* __restrict__ bias, const float* __restrict__ res,
    float* __restrict__ Cf,
    __nv_bfloat16* __restrict__ Ch, __nv_bfloat16* __restrict__ Cl,
    int M, int N, int K)
{
    extern __shared__ __align__(16) char smem[];
    const uint32_t sb = smem_u32(smem);
    const int tid  = threadIdx.x;
    const int lane = tid & 31;
    const int w    = tid >> 5;
    const int wm   = w & 1;
    const int wn   = w >> 1;
    const int m0   = blockIdx.y * 128, n0 = blockIdx.x * 128;

    float acc[4][4][4];
    #pragma unroll
    for (int mi = 0; mi < 4; mi++)
        #pragma unroll
        for (int ni = 0; ni < 4; ni++)
            #pragma unroll
            for (int t = 0; t < 4; t++) acc[mi][ni][t] = 0.f;

    const int nc = K >> 5;

    auto load_stage = [&](int st, int c) {
        const int k0 = c << 5;
        const uint32_t stb = sb + (uint32_t)(st * STG * 2);
        #pragma unroll
        for (int i = 0; i < 2; i++) {
            const int id  = tid + i * 256;
            const int row = id >> 2, seg = id & 3;
            const uint32_t d = (uint32_t)((row * AP + seg * 8) * 2);
            const size_t ga = (size_t)(m0 + row) * K + k0 + seg * 8;
            const size_t gb = (size_t)(n0 + row) * K + k0 + seg * 8;
            cp16(stb + d,               Ah + ga);
            cp16(stb + TSZ * 2 + d,     Al + ga);
            cp16(stb + 2 * TSZ * 2 + d, Bh + gb);
            cp16(stb + 3 * TSZ * 2 + d, Bl + gb);
        }
    };

    load_stage(0, 0);
    asm volatile("cp.async.commit_group;");

    for (int c = 0; c < nc; c++) {
        if (c + 1 < nc) load_stage((c + 1) & 1, c + 1);
        asm volatile("cp.async.commit_group;");
        asm volatile("cp.async.wait_group 1;");
        __syncthreads();

        const uint32_t stb = sb + (uint32_t)((c & 1) * STG * 2);
        #pragma unroll
        for (int ks = 0; ks < 2; ks++) {
            uint32_t bh[4][2], bl[4][2];
            #pragma unroll
            for (int np = 0; np < 2; np++) {
                const int row = wn * 32 + np * 16 + ((lane >> 4) & 1) * 8 + (lane & 7);
                const int col = ks * 16 + ((lane >> 3) & 1) * 8;
                const uint32_t off = stb + 2 * TSZ * 2 + (uint32_t)((row * AP + col) * 2);
                uint32_t r[4];
                ldm_x4(r, off);
                bh[np * 2][0] = r[0]; bh[np * 2][1] = r[1];
                bh[np * 2 + 1][0] = r[2]; bh[np * 2 + 1][1] = r[3];
                ldm_x4(r, off + TSZ * 2);
                bl[np * 2][0] = r[0]; bl[np * 2][1] = r[1];
                bl[np * 2 + 1][0] = r[2]; bl[np * 2 + 1][1] = r[3];
            }
            #pragma unroll
            for (int mi = 0; mi < 4; mi++) {
                const int row = wm * 64 + mi * 16 + (lane & 15);
                const int col = ks * 16 + (lane >> 4) * 8;
                const uint32_t off = stb + (uint32_t)((row * AP + col) * 2);
                uint32_t ah[4], al[4];
                ldm_x4(ah, off);
                ldm_x4(al, off + TSZ * 2);
                #pragma unroll
                for (int ni = 0; ni < 4; ni++) {
                    mma16816(acc[mi][ni], ah, bh[ni]);
                    mma16816(acc[mi][ni], ah, bl[ni]);
                    mma16816(acc[mi][ni], al, bh[ni]);
                }
            }
        }
        __syncthreads();
    }

    // --- epilogue ---
    const int rbase = m0 + wm * 64 + (lane >> 2);
    const int cbase = n0 + wn * 32 + (lane & 3) * 2;
    #pragma unroll
    for (int mi = 0; mi < 4; mi++) {
        #pragma unroll
        for (int ni = 0; ni < 4; ni++) {
            #pragma unroll
            for (int half = 0; half < 2; half++) {
                const int m = rbase + mi * 16 + half * 8;
                const int n = cbase + ni * 8;
                float v0 = acc[mi][ni][half * 2];
                float v1 = acc[mi][ni][half * 2 + 1];
                const size_t o = (size_t)m * N + n;
                if (EPI == 2) {
                    const float2 r2 = *(const float2*)(res + o);
                    float2 t = {v0 + bias[n] + r2.x, v1 + bias[n + 1] + r2.y};
                    *(float2*)(Cf + o) = t;
                } else {  // EPI == 3
                    float u0 = v0 + bias[n];
                    float u1 = v1 + bias[n + 1];
                    const float i0 = 0.7978845608028654f * (u0 + 0.044715f * u0 * u0 * u0);
                    const float i1 = 0.7978845608028654f * (u1 + 0.044715f * u1 * u1 * u1);
                    const float g0 = 0.5f * u0 * (1.f + tanhf(i0));
                    const float g1 = 0.5f * u1 * (1.f + tanhf(i1));
                    const __nv_bfloat16 h0 = __float2bfloat16(g0);
                    const __nv_bfloat16 h1 = __float2bfloat16(g1);
                    __nv_bfloat162 hp, lp;
                    hp.x = h0; hp.y = h1;
                    lp.x = __float2bfloat16(g0 - __bfloat162float(h0));
                    lp.y = __float2bfloat16(g1 - __bfloat162float(h1));
                    *(__nv_bfloat162*)(Ch + o) = hp;
                    *(__nv_bfloat162*)(Cl + o) = lp;
                }
            }
        }
    }
}

// ---------------------------------------------------------------------------
// HMMA causal flash attention, single-bf16 Q/K/V, split P. (unchanged R10)
// Grid (32, 12, 2), 128 threads, forced 4 CTAs/SM.
// ---------------------------------------------------------------------------
__global__ __launch_bounds__(128, 4) void attn_mma(
    const __nv_bfloat16* __restrict__ qkv,
    __nv_bfloat16* __restrict__ ch, __nv_bfloat16* __restrict__ cl)
{
    extern __shared__ __align__(16) char smem[];
    const uint32_t sb = smem_u32(smem);
    const int tid = threadIdx.x, lane = tid & 31, w = tid >> 5;
    const int qt = (int)gridDim.x - 1 - (int)blockIdx.x;
    const int h = blockIdx.y, b = blockIdx.z;
    const int wq0 = w * 16;
    const int colb = h * 64;

    {
        const int rbase = b * Tt + qt * 64;
        #pragma unroll
        for (int i = 0; i < 4; i++) {
            const int t2 = tid + i * 128;
            const int row = t2 >> 3, seg = (t2 & 7) * 8;
            const size_t src = (size_t)(rbase + row) * QKV3 + colb + seg;
            cp16(sb + (uint32_t)((row * APAD + seg) * 2), qkv + src);
        }
    }
    asm volatile("cp.async.commit_group;");
    asm volatile("cp.async.wait_group 0;");
    __syncthreads();

    uint32_t qh[4][4];
    #pragma unroll
    for (int ks = 0; ks < 4; ks++) {
        const int row = wq0 + (lane & 15);
        const int col = ks * 16 + (lane >> 4) * 8;
        ldm_x4(qh[ks], sb + (uint32_t)((row * APAD + col) * 2));
    }
    __syncthreads();

    auto load_kv = [&](int st, int kt) {
        const int rbase = b * Tt + kt * 64;
        #pragma unroll
        for (int i = 0; i < 4; i++) {
            const int t2 = tid + i * 128;
            const int row = t2 >> 3, seg = (t2 & 7) * 8;
            const size_t srcK = (size_t)(rbase + row) * QKV3 + Dd + colb + seg;
            const uint32_t dst = sb + (uint32_t)((st * ASTG + row * APAD + seg) * 2);
            cp16(dst,             qkv + srcK);        // K
            cp16(dst + ATILE * 2, qkv + srcK + Dd);   // V
        }
    };

    float oacc[8][4];
    #pragma unroll
    for (int i = 0; i < 8; i++)
        #pragma unroll
        for (int t = 0; t < 4; t++) oacc[i][t] = 0.f;
    float m0 = -1e30f, m1 = -1e30f, l0 = 0.f, l1 = 0.f;

    load_kv(0, 0);
    asm volatile("cp.async.commit_group;");

    const int r0 = lane >> 2, c0 = (lane & 3) * 2;

    for (int kt = 0; kt <= qt; kt++) {
        if (kt < qt) load_kv((kt + 1) & 1, kt + 1);
        asm volatile("cp.async.commit_group;");
        asm volatile("cp.async.wait_group 1;");
        __syncthreads();
        const uint32_t stb = sb + (uint32_t)((kt & 1) * ASTG * 2);

        float sacc[8][4];
        #pragma unroll
        for (int i = 0; i < 8; i++)
            #pragma unroll
            for (int t = 0; t < 4; t++) sacc[i][t] = 0.f;

        #pragma unroll
        for (int ks = 0; ks < 4; ks++) {
            #pragma unroll
            for (int np = 0; np < 4; np++) {
                const int row = np * 16 + ((lane >> 4) & 1) * 8 + (lane & 7);
                const int col = ks * 16 + ((lane >> 3) & 1) * 8;
                uint32_t rk[4];
                ldm_x4(rk, stb + (uint32_t)((row * APAD + col) * 2));
                uint32_t b0[2] = {rk[0], rk[1]}, b1[2] = {rk[2], rk[3]};
                mma16816(sacc[np * 2],     qh[ks], b0);
                mma16816(sacc[np * 2 + 1], qh[ks], b1);
            }
        }

        const bool diag = (kt == qt);
        #pragma unroll
        for (int nt = 0; nt < 8; nt++) {
            #pragma unroll
            for (int e = 0; e < 4; e++) {
                float sv = sacc[nt][e] * 0.125f;
                if (diag) {
                    const int rr = wq0 + r0 + ((e >> 1) << 3);
                    const int cc = nt * 8 + c0 + (e & 1);
                    if (cc > rr) sv = -1e30f;
                }
                sacc[nt][e] = sv;
            }
        }

        float mx0 = -1e30f, mx1 = -1e30f;
        #pragma unroll
        for (int nt = 0; nt < 8; nt++) {
            mx0 = fmaxf(mx0, fmaxf(sacc[nt][0], sacc[nt][1]));
            mx1 = fmaxf(mx1, fmaxf(sacc[nt][2], sacc[nt][3]));
        }
        mx0 = fmaxf(mx0, __shfl_xor_sync(0xffffffffu, mx0, 1));
        mx0 = fmaxf(mx0, __shfl_xor_sync(0xffffffffu, mx0, 2));
        mx1 = fmaxf(mx1, __shfl_xor_sync(0xffffffffu, mx1, 1));
        mx1 = fmaxf(mx1, __shfl_xor_sync(0xffffffffu, mx1, 2));
        const float mn0 = fmaxf(m0, mx0), mn1 = fmaxf(m1, mx1);
        const float sc0 = __expf(m0 - mn0), sc1 = __expf(m1 - mn1);
        m0 = mn0; m1 = mn1;

        uint32_t ph[4][4], pl[4][4];
        float s0 = 0.f, s1 = 0.f;
        #pragma unroll
        for (int nt = 0; nt < 8; nt++) {
            const float p0 = __expf(sacc[nt][0] - mn0);
            const float p1 = __expf(sacc[nt][1] - mn0);
            const float p2 = __expf(sacc[nt][2] - mn1);
            const float p3 = __expf(sacc[nt][3] - mn1);
            s0 += p0 + p1; s1 += p2 + p3;
            const float h0 = __bfloat162float(__float2bfloat16(p0));
            const float h1 = __bfloat162float(__float2bfloat16(p1));
            const float h2 = __bfloat162float(__float2bfloat16(p2));
            const float h3 = __bfloat162float(__float2bfloat16(p3));
            const int ks2 = nt >> 1, hf = (nt & 1) * 2;
            ph[ks2][hf]     = packbf(h0, h1);
            ph[ks2][hf + 1] = packbf(h2, h3);
            pl[ks2][hf]     = packbf(p0 - h0, p1 - h1);
            pl[ks2][hf + 1] = packbf(p2 - h2, p3 - h3);
        }
        s0 += __shfl_xor_sync(0xffffffffu, s0, 1);
        s0 += __shfl_xor_sync(0xffffffffu, s0, 2);
        s1 += __shfl_xor_sync(0xffffffffu, s1, 1);
        s1 += __shfl_xor_sync(0xffffffffu, s1, 2);
        l0 = l0 * sc0 + s0;
        l1 = l1 * sc1 + s1;

        #pragma unroll
        for (int dt = 0; dt < 8; dt++) {
            oacc[dt][0] *= sc0; oacc[dt][1] *= sc0;
            oacc[dt][2] *= sc1; oacc[dt][3] *= sc1;
        }

        const uint32_t vtb = stb + ATILE * 2;
        #pragma unroll
        for (int ks = 0; ks < 4; ks++) {
            #pragma unroll
            for (int dp = 0; dp < 4; dp++) {
                const int krow = 16 * ks + (lane & 15);
                const int ncol = dp * 16 + (lane >> 4) * 8;
                uint32_t rv[4];
                ldm_x4_t(rv, vtb + (uint32_t)((krow * APAD + ncol) * 2));
                uint32_t v0[2] = {rv[0], rv[1]}, v1[2] = {rv[2], rv[3]};
                mma16816(oacc[dp * 2],     ph[ks], v0);
                mma16816(oacc[dp * 2],     pl[ks], v0);
                mma16816(oacc[dp * 2 + 1], ph[ks], v1);
                mma16816(oacc[dp * 2 + 1], pl[ks], v1);
            }
        }
        __syncthreads();
    }

    const float inv0 = 1.f / l0, inv1 = 1.f / l1;
    const size_t rg0 = (size_t)(b * Tt + qt * 64 + wq0 + r0);
    #pragma unroll
    for (int dt = 0; dt < 8; dt++) {
        const int col = colb + dt * 8 + c0;
        {
            const float v0 = oacc[dt][0] * inv0, v1 = oacc[dt][1] * inv0;
            const __nv_bfloat16 h0 = __float2bfloat16(v0);
            const __nv_bfloat16 h1 = __float2bfloat16(v1);
            __nv_bfloat162 hp, lp;
            hp.x = h0; hp.y = h1;
            lp.x = __float2bfloat16(v0 - __bfloat162float(h0));
            lp.y = __float2bfloat16(v1 - __bfloat162float(h1));
            *(__nv_bfloat162*)(ch + rg0 * Dd + col) = hp;
            *(__nv_bfloat162*)(cl + rg0 * Dd + col) = lp;
        }
        {
            const float v0 = oacc[dt][2] * inv1, v1 = oacc[dt][3] * inv1;
            const __nv_bfloat16 h0 = __float2bfloat16(v0);
            const __nv_bfloat16 h1 = __float2bfloat16(v1);
            __nv_bfloat162 hp, lp;
            hp.x = h0; hp.y = h1;
            lp.x = __float2bfloat16(v0 - __bfloat162float(h0));
            lp.y = __float2bfloat16(v1 - __bfloat162float(h1));
            *(__nv_bfloat162*)(ch + (rg0 + 8) * Dd + col) = hp;
            *(__nv_bfloat162*)(cl + (rg0 + 8) * Dd + col) = lp;
        }
    }
}

// ---------------------------------------------------------------------------
// Launch
// ---------------------------------------------------------------------------
extern "C" void kernel_launch(void* const* d_in, const int* in_sizes, int n_in,
                              void* d_out, int out_size)
{
    const float* x    = (const float*)d_in[0];
    const float* ln1s = (const float*)d_in[1];
    const float* ln1b = (const float*)d_in[2];
    const float* wq   = (const float*)d_in[3];
    const float* wk   = (const float*)d_in[4];
    const float* wv   = (const float*)d_in[5];
    const float* wo   = (const float*)d_in[6];
    const float* bo   = (const float*)d_in[7];
    const float* ln2s = (const float*)d_in[8];
    const float* ln2b = (const float*)d_in[9];
    const float* w1   = (const float*)d_in[10];
    const float* b1   = (const float*)d_in[11];
    const float* w2   = (const float*)d_in[12];
    const float* b2   = (const float*)d_in[13];
    float* out = (float*)d_out;

    float* x1;
    cudaGetSymbolAddress((void**)&x1, g_x1);

    __nv_bfloat16 *xnh, *xnl, *qkv, *ctxh, *ctxl, *hh, *hl;
    __nv_bfloat16 *wqkvh, *wqkvl, *woh, *wol, *w1h, *w1l, *w2h, *w2l;
    cudaGetSymbolAddress((void**)&xnh,   g_xn_h);
    cudaGetSymbolAddress((void**)&xnl,   g_xn_l);
    cudaGetSymbolAddress((void**)&qkv,   g_qkv);
    cudaGetSymbolAddress((void**)&ctxh,  g_ctx_h);
    cudaGetSymbolAddress((void**)&ctxl,  g_ctx_l);
    cudaGetSymbolAddress((void**)&hh,    g_h_h);
    cudaGetSymbolAddress((void**)&hl,    g_h_l);
    cudaGetSymbolAddress((void**)&wqkvh, g_wqkv_h);
    cudaGetSymbolAddress((void**)&wqkvl, g_wqkv_l);
    cudaGetSymbolAddress((void**)&woh,   g_wo_h);
    cudaGetSymbolAddress((void**)&wol,   g_wo_l);
    cudaGetSymbolAddress((void**)&w1h,   g_w1_h);
    cudaGetSymbolAddress((void**)&w1l,   g_w1_l);
    cudaGetSymbolAddress((void**)&w2h,   g_w2_h);
    cudaGetSymbolAddress((void**)&w2l,   g_w2_l);

    cudaFuncSetAttribute(attn_mma,
                         cudaFuncAttributeMaxDynamicSharedMemorySize, ATTN_SMEM2);
    cudaFuncSetAttribute(gemm_plain,
                         cudaFuncAttributeMaxDynamicSharedMemorySize, PSMEM_BYTES);
    cudaFuncSetAttribute(gemm_mma<2>,
                         cudaFuncAttributeMaxDynamicSharedMemorySize, GSMEM_BYTES);
    cudaFuncSetAttribute(gemm_mma<3>,
                         cudaFuncAttributeMaxDynamicSharedMemorySize, GSMEM_BYTES);

    // All weight conversions in one launch
    cvt_weights<<<(CVT_TOTAL + 255) / 256, 256>>>(
        wq, wk, wv, wo, w1, w2,
        wqkvh, wqkvl, woh, wol, w1h, w1l, w2h, w2l);

    // LN1 -> xn (hi/lo)
    ln_hilo<<<MROWS, 256>>>(x, ln1s, ln1b, xnh, xnl);

    // Fused QKV projection, PLAIN bf16 -> qkv, N = 2304
    dim3 gqkv(QKV3 / 128, MROWS / 128);
    gemm_plain<<<gqkv, 256, PSMEM_BYTES>>>(xnh, wqkvh, qkv, MROWS, QKV3, Dd);

    // Attention (HMMA flash) -> ctx (hi/lo bf16)
    dim3 ga(Tt / 64, Hh, Bb);
    attn_mma<<<ga, 128, ATTN_SMEM2>>>(qkv, ctxh, ctxl);

    // O projection + bias + residual -> x1 (fp32)
    dim3 gdd(Dd / 128, MROWS / 128);
    gemm_mma<2><<<gdd, 256, GSMEM_BYTES>>>(ctxh, ctxl, woh, wol, bo, x,
                                           x1, nullptr, nullptr, MROWS, Dd, Dd);

    // LN2 -> xn (hi/lo)
    ln_hilo<<<MROWS, 256>>>(x1, ln2s, ln2b, xnh, xnl);

    // MLP1: bias + GELU -> h (hi/lo bf16)
    dim3 g1(DFF / 128, MROWS / 128);
    gemm_mma<3><<<g1, 256, GSMEM_BYTES>>>(xnh, xnl, w1h, w1l, b1, nullptr,
                                          nullptr, hh, hl, MROWS, DFF, Dd);

    // MLP2: bias + residual -> out (fp32)
    gemm_mma<2><<<gdd, 256, GSMEM_BYTES>>>(hh, hl, w2h, w2l, b2, x1,
                                           out, nullptr, nullptr, MROWS, Dd, DFF);
}

// round 14
// speedup vs baseline: 1.6466x; 1.2874x over previous
#include <cuda_runtime.h>
#include <cuda_bf16.h>
#include <math.h>
#include <cstdint>

// ---------------------------------------------------------------------------
// Problem constants
// ---------------------------------------------------------------------------
namespace {
constexpr int Bb   = 2;
constexpr int Tt   = 2048;
constexpr int Dd   = 768;
constexpr int QKV3 = 3 * Dd;       // 2304
constexpr int Hh   = 12;
constexpr int MROWS = Bb * Tt;     // 4096
constexpr int DFF   = 4 * Dd;      // 3072
constexpr int NDD  = Dd * Dd;      // 589824
constexpr int NW1  = DFF * Dd;     // 2359296
constexpr int CVT_TOTAL = 4 * NDD + 2 * NW1;  // 7077888

// GEMM tiling: CTA 128x128, BK=32, 2-stage cp.async pipeline
constexpr int AP   = 40;             // padded row length (bf16 elems), 80B
constexpr int TSZ  = 128 * AP;       // elems per tile: 5120

// 2-term split GEMM: per stage (A, Bh, Bl)
constexpr int STG2 = 3 * TSZ;        // 15360
constexpr int GSMEM_BYTES = 2 * STG2 * 2;  // 61440

// plain GEMM: per stage (A, B)
constexpr int PSTG = 2 * TSZ;        // 10240
constexpr int PSMEM_BYTES = 2 * PSTG * 2;  // 40960

// attention smem: 2 stages x (K, V) 64x72 bf16 tiles
constexpr int APAD = 72;
constexpr int ATILE = 64 * APAD;        // 4608 elems
constexpr int ASTG  = 2 * ATILE;        // 9216 elems per stage
constexpr int ATTN_SMEM2 = 2 * ASTG * 2;  // 36864 bytes
}

// ---------------------------------------------------------------------------
// Scratch (no allocation allowed)
// ---------------------------------------------------------------------------
__device__ float g_x1 [MROWS * Dd];

__device__ __nv_bfloat16 g_xn    [MROWS * Dd];
__device__ __nv_bfloat16 g_qkv   [MROWS * QKV3];
__device__ __nv_bfloat16 g_ctx   [MROWS * Dd];
__device__ __nv_bfloat16 g_h     [MROWS * DFF];
__device__ __nv_bfloat16 g_wqkv_h[QKV3 * Dd],   g_wqkv_l[QKV3 * Dd];
__device__ __nv_bfloat16 g_wo_h  [Dd * Dd],     g_wo_l  [Dd * Dd];
__device__ __nv_bfloat16 g_w1_h  [DFF * Dd],    g_w1_l  [DFF * Dd];
__device__ __nv_bfloat16 g_w2_h  [Dd * DFF],    g_w2_l  [Dd * DFF];

// ---------------------------------------------------------------------------
// PTX helpers (baseline PTX, legal at compute_100)
// ---------------------------------------------------------------------------
__device__ __forceinline__ uint32_t smem_u32(const void* p) {
    uint32_t a;
    asm("{ .reg .u64 t; cvta.to.shared.u64 t, %1; cvt.u32.u64 %0, t; }"
        : "=r"(a) : "l"(p));
    return a;
}

__device__ __forceinline__ void cp16(uint32_t dst, const void* src) {
    asm volatile("cp.async.cg.shared.global [%0], [%1], 16;" :: "r"(dst), "l"(src));
}

__device__ __forceinline__ void ldm_x4(uint32_t* r, uint32_t addr) {
    asm volatile("ldmatrix.sync.aligned.m8n8.x4.shared.b16 {%0,%1,%2,%3}, [%4];"
        : "=r"(r[0]), "=r"(r[1]), "=r"(r[2]), "=r"(r[3]) : "r"(addr));
}

__device__ __forceinline__ void ldm_x4_t(uint32_t* r, uint32_t addr) {
    asm volatile("ldmatrix.sync.aligned.m8n8.x4.trans.shared.b16 {%0,%1,%2,%3}, [%4];"
        : "=r"(r[0]), "=r"(r[1]), "=r"(r[2]), "=r"(r[3]) : "r"(addr));
}

__device__ __forceinline__ void mma16816(float* c, const uint32_t* a, const uint32_t* b) {
    asm volatile(
        "mma.sync.aligned.m16n8k16.row.col.f32.bf16.bf16.f32 "
        "{%0,%1,%2,%3}, {%4,%5,%6,%7}, {%8,%9}, {%0,%1,%2,%3};"
        : "+f"(c[0]), "+f"(c[1]), "+f"(c[2]), "+f"(c[3])
        : "r"(a[0]), "r"(a[1]), "r"(a[2]), "r"(a[3]), "r"(b[0]), "r"(b[1]));
}

// pack two floats to bf16x2 (lo = first arg)
__device__ __forceinline__ uint32_t packbf(float lo, float hi) {
    uint32_t r;
    asm("cvt.rn.bf16x2.f32 %0, %1, %2;" : "=r"(r) : "f"(hi), "f"(lo));
    return r;
}

// ---------------------------------------------------------------------------
// LayerNorm -> bf16
// ---------------------------------------------------------------------------
__global__ __launch_bounds__(256) void ln_bf16(
    const float* __restrict__ x, const float* __restrict__ sc,
    const float* __restrict__ sh, __nv_bfloat16* __restrict__ oh)
{
    const int row = blockIdx.x;
    const float* xr = x + (size_t)row * Dd;
    __shared__ float s1[256], s2[256];
    float a = 0.f, b = 0.f;
    for (int i = threadIdx.x; i < Dd; i += 256) {
        float v = xr[i];
        a += v; b += v * v;
    }
    s1[threadIdx.x] = a; s2[threadIdx.x] = b;
    __syncthreads();
    for (int off = 128; off > 0; off >>= 1) {
        if (threadIdx.x < off) {
            s1[threadIdx.x] += s1[threadIdx.x + off];
            s2[threadIdx.x] += s2[threadIdx.x + off];
        }
        __syncthreads();
    }
    const float mean = s1[0] * (1.f / Dd);
    const float var  = s2[0] * (1.f / Dd) - mean * mean;
    const float rstd = rsqrtf(var + 1e-5f);
    for (int i = threadIdx.x; i < Dd; i += 256) {
        const float v = sc[i] * (xr[i] - mean) * rstd + sh[i];
        oh[(size_t)row * Dd + i] = __float2bfloat16(v);
    }
}

// ---------------------------------------------------------------------------
// All six weight matrices -> (hi, lo) bf16 in ONE launch.
// ---------------------------------------------------------------------------
__global__ __launch_bounds__(256) void cvt_weights(
    const float* __restrict__ wq, const float* __restrict__ wk,
    const float* __restrict__ wv, const float* __restrict__ wo,
    const float* __restrict__ w1, const float* __restrict__ w2,
    __nv_bfloat16* __restrict__ wqkvh, __nv_bfloat16* __restrict__ wqkvl,
    __nv_bfloat16* __restrict__ woh,   __nv_bfloat16* __restrict__ wol,
    __nv_bfloat16* __restrict__ w1h,   __nv_bfloat16* __restrict__ w1l,
    __nv_bfloat16* __restrict__ w2h,   __nv_bfloat16* __restrict__ w2l)
{
    const int gid = blockIdx.x * 256 + threadIdx.x;
    if (gid >= CVT_TOTAL) return;
    float v;
    __nv_bfloat16 *dh, *dl;
    if (gid < 3 * NDD) {
        v = (gid < NDD) ? wq[gid] : (gid < 2 * NDD) ? wk[gid - NDD] : wv[gid - 2 * NDD];
        dh = wqkvh + gid; dl = wqkvl + gid;
    } else if (gid < 4 * NDD) {
        const int j = gid - 3 * NDD;
        v = wo[j]; dh = woh + j; dl = wol + j;
    } else if (gid < 4 * NDD + NW1) {
        const int j = gid - 4 * NDD;
        v = w1[j]; dh = w1h + j; dl = w1l + j;
    } else {
        const int j = gid - 4 * NDD - NW1;
        v = w2[j]; dh = w2h + j; dl = w2l + j;
    }
    const __nv_bfloat16 h = __float2bfloat16(v);
    *dh = h;
    *dl = __float2bfloat16(v - __bfloat162float(h));
}

// ---------------------------------------------------------------------------
// PLAIN bf16 NT GEMM: C = A * B^T, single bf16 out (QKV projection).
// CTA 128x128, BK=32, 256 thr = 8 warps (2m x 4n), warp tile 64x32.
// ---------------------------------------------------------------------------
__global__ __launch_bounds__(256, 2) void gemm_plain(
    const __nv_bfloat16* __restrict__ A, const __nv_bfloat16* __restrict__ B,
    __nv_bfloat16* __restrict__ C, int M, int N, int K)
{
    extern __shared__ __align__(16) char smem[];
    const uint32_t sb = smem_u32(smem);
    const int tid  = threadIdx.x;
    const int lane = tid & 31;
    const int w    = tid >> 5;
    const int wm   = w & 1;
    const int wn   = w >> 1;
    const int m0   = blockIdx.y * 128, n0 = blockIdx.x * 128;

    float acc[4][4][4];
    #pragma unroll
    for (int mi = 0; mi < 4; mi++)
        #pragma unroll
        for (int ni = 0; ni < 4; ni++)
            #pragma unroll
            for (int t = 0; t < 4; t++) acc[mi][ni][t] = 0.f;

    const int nc = K >> 5;

    auto load_stage = [&](int st, int c) {
        const int k0 = c << 5;
        const uint32_t stb = sb + (uint32_t)(st * PSTG * 2);
        #pragma unroll
        for (int i = 0; i < 2; i++) {
            const int id  = tid + i * 256;
            const int row = id >> 2, seg = id & 3;
            const uint32_t d = (uint32_t)((row * AP + seg * 8) * 2);
            cp16(stb + d,           A + (size_t)(m0 + row) * K + k0 + seg * 8);
            cp16(stb + TSZ * 2 + d, B + (size_t)(n0 + row) * K + k0 + seg * 8);
        }
    };

    load_stage(0, 0);
    asm volatile("cp.async.commit_group;");

    for (int c = 0; c < nc; c++) {
        if (c + 1 < nc) load_stage((c + 1) & 1, c + 1);
        asm volatile("cp.async.commit_group;");
        asm volatile("cp.async.wait_group 1;");
        __syncthreads();

        const uint32_t stb = sb + (uint32_t)((c & 1) * PSTG * 2);
        #pragma unroll
        for (int ks = 0; ks < 2; ks++) {
            uint32_t bb[4][2];
            #pragma unroll
            for (int np = 0; np < 2; np++) {
                const int row = wn * 32 + np * 16 + ((lane >> 4) & 1) * 8 + (lane & 7);
                const int col = ks * 16 + ((lane >> 3) & 1) * 8;
                uint32_t r[4];
                ldm_x4(r, stb + TSZ * 2 + (uint32_t)((row * AP + col) * 2));
                bb[np * 2][0] = r[0]; bb[np * 2][1] = r[1];
                bb[np * 2 + 1][0] = r[2]; bb[np * 2 + 1][1] = r[3];
            }
            #pragma unroll
            for (int mi = 0; mi < 4; mi++) {
                const int row = wm * 64 + mi * 16 + (lane & 15);
                const int col = ks * 16 + (lane >> 4) * 8;
                uint32_t aa[4];
                ldm_x4(aa, stb + (uint32_t)((row * AP + col) * 2));
                #pragma unroll
                for (int ni = 0; ni < 4; ni++)
                    mma16816(acc[mi][ni], aa, bb[ni]);
            }
        }
        __syncthreads();
    }

    const int rbase = m0 + wm * 64 + (lane >> 2);
    const int cbase = n0 + wn * 32 + (lane & 3) * 2;
    #pragma unroll
    for (int mi = 0; mi < 4; mi++)
        #pragma unroll
        for (int ni = 0; ni < 4; ni++)
            #pragma unroll
            for (int half = 0; half < 2; half++) {
                const int m = rbase + mi * 16 + half * 8;
                const int n = cbase + ni * 8;
                __nv_bfloat162 hp;
                hp.x = __float2bfloat16(acc[mi][ni][half * 2]);
                hp.y = __float2bfloat16(acc[mi][ni][half * 2 + 1]);
                *(__nv_bfloat162*)(C + (size_t)m * N + n) = hp;
            }
}

// ---------------------------------------------------------------------------
// 2-term split GEMM: C = A * (Bh + Bl)^T  (activation single bf16, weight split)
// EPI: 2 = +bias +res, fp32 out; 3 = +bias, GELU, bf16 out
// CTA 128x128, BK=32, 256 thr = 8 warps (2m x 4n), warp tile 64x32
// ---------------------------------------------------------------------------
template<int EPI>
__global__ __launch_bounds__(256, 2) void gemm_mma2(
    const __nv_bfloat16* __restrict__ A,
    const __nv_bfloat16* __restrict__ Bh, const __nv_bfloat16* __restrict__ Bl,
    const float* __restrict__ bias, const float* __restrict__ res,
    float* __restrict__ Cf, __nv_bfloat16* __restrict__ Ch,
    int M, int N, int K)
{
    extern __shared__ __align__(16) char smem[];
    const uint32_t sb = smem_u32(smem);
    const int tid  = threadIdx.x;
    const int lane = tid & 31;
    const int w    = tid >> 5;
    const int wm   = w & 1;
    const int wn   = w >> 1;
    const int m0   = blockIdx.y * 128, n0 = blockIdx.x * 128;

    float acc[4][4][4];
    #pragma unroll
    for (int mi = 0; mi < 4; mi++)
        #pragma unroll
        for (int ni = 0; ni < 4; ni++)
            #pragma unroll
            for (int t = 0; t < 4; t++) acc[mi][ni][t] = 0.f;

    const int nc = K >> 5;

    // stage layout: A:0, Bh:TSZ, Bl:2*TSZ
    auto load_stage = [&](int st, int c) {
        const int k0 = c << 5;
        const uint32_t stb = sb + (uint32_t)(st * STG2 * 2);
        #pragma unroll
        for (int i = 0; i < 2; i++) {
            const int id  = tid + i * 256;
            const int row = id >> 2, seg = id & 3;
            const uint32_t d = (uint32_t)((row * AP + seg * 8) * 2);
            const size_t ga = (size_t)(m0 + row) * K + k0 + seg * 8;
            const size_t gb = (size_t)(n0 + row) * K + k0 + seg * 8;
            cp16(stb + d,               A  + ga);
            cp16(stb + TSZ * 2 + d,     Bh + gb);
            cp16(stb + 2 * TSZ * 2 + d, Bl + gb);
        }
    };

    load_stage(0, 0);
    asm volatile("cp.async.commit_group;");

    for (int c = 0; c < nc; c++) {
        if (c + 1 < nc) load_stage((c + 1) & 1, c + 1);
        asm volatile("cp.async.commit_group;");
        asm volatile("cp.async.wait_group 1;");
        __syncthreads();

        const uint32_t stb = sb + (uint32_t)((c & 1) * STG2 * 2);
        #pragma unroll
        for (int ks = 0; ks < 2; ks++) {
            uint32_t bh[4][2], bl[4][2];
            #pragma unroll
            for (int np = 0; np < 2; np++) {
                const int row = wn * 32 + np * 16 + ((lane >> 4) & 1) * 8 + (lane & 7);
                const int col = ks * 16 + ((lane >> 3) & 1) * 8;
                const uint32_t off = stb + TSZ * 2 + (uint32_t)((row * AP + col) * 2);
                uint32_t r[4];
                ldm_x4(r, off);
                bh[np * 2][0] = r[0]; bh[np * 2][1] = r[1];
                bh[np * 2 + 1][0] = r[2]; bh[np * 2 + 1][1] = r[3];
                ldm_x4(r, off + TSZ * 2);
                bl[np * 2][0] = r[0]; bl[np * 2][1] = r[1];
                bl[np * 2 + 1][0] = r[2]; bl[np * 2 + 1][1] = r[3];
            }
            #pragma unroll
            for (int mi = 0; mi < 4; mi++) {
                const int row = wm * 64 + mi * 16 + (lane & 15);
                const int col = ks * 16 + (lane >> 4) * 8;
                uint32_t aa[4];
                ldm_x4(aa, stb + (uint32_t)((row * AP + col) * 2));
                #pragma unroll
                for (int ni = 0; ni < 4; ni++) {
                    mma16816(acc[mi][ni], aa, bh[ni]);
                    mma16816(acc[mi][ni], aa, bl[ni]);
                }
            }
        }
        __syncthreads();
    }

    // --- epilogue ---
    const int rbase = m0 + wm * 64 + (lane >> 2);
    const int cbase = n0 + wn * 32 + (lane & 3) * 2;
    #pragma unroll
    for (int mi = 0; mi < 4; mi++) {
        #pragma unroll
        for (int ni = 0; ni < 4; ni++) {
            #pragma unroll
            for (int half = 0; half < 2; half++) {
                const int m = rbase + mi * 16 + half * 8;
                const int n = cbase + ni * 8;
                float v0 = acc[mi][ni][half * 2];
                float v1 = acc[mi][ni][half * 2 + 1];
                const size_t o = (size_t)m * N + n;
                if (EPI == 2) {
                    const float2 r2 = *(const float2*)(res + o);
                    float2 t = {v0 + bias[n] + r2.x, v1 + bias[n + 1] + r2.y};
                    *(float2*)(Cf + o) = t;
                } else {  // EPI == 3: bias + GELU -> bf16
                    float u0 = v0 + bias[n];
                    float u1 = v1 + bias[n + 1];
                    const float i0 = 0.7978845608028654f * (u0 + 0.044715f * u0 * u0 * u0);
                    const float i1 = 0.7978845608028654f * (u1 + 0.044715f * u1 * u1 * u1);
                    const float g0 = 0.5f * u0 * (1.f + tanhf(i0));
                    const float g1 = 0.5f * u1 * (1.f + tanhf(i1));
                    __nv_bfloat162 hp;
                    hp.x = __float2bfloat16(g0);
                    hp.y = __float2bfloat16(g1);
                    *(__nv_bfloat162*)(Ch + o) = hp;
                }
            }
        }
    }
}

// ---------------------------------------------------------------------------
// HMMA causal flash attention, single-bf16 Q/K/V, split P, bf16 ctx out.
// Grid (32, 12, 2), 128 threads, forced 4 CTAs/SM.
// ---------------------------------------------------------------------------
__global__ __launch_bounds__(128, 4) void attn_mma(
    const __nv_bfloat16* __restrict__ qkv, __nv_bfloat16* __restrict__ ch)
{
    extern __shared__ __align__(16) char smem[];
    const uint32_t sb = smem_u32(smem);
    const int tid = threadIdx.x, lane = tid & 31, w = tid >> 5;
    const int qt = (int)gridDim.x - 1 - (int)blockIdx.x;
    const int h = blockIdx.y, b = blockIdx.z;
    const int wq0 = w * 16;
    const int colb = h * 64;

    {
        const int rbase = b * Tt + qt * 64;
        #pragma unroll
        for (int i = 0; i < 4; i++) {
            const int t2 = tid + i * 128;
            const int row = t2 >> 3, seg = (t2 & 7) * 8;
            const size_t src = (size_t)(rbase + row) * QKV3 + colb + seg;
            cp16(sb + (uint32_t)((row * APAD + seg) * 2), qkv + src);
        }
    }
    asm volatile("cp.async.commit_group;");
    asm volatile("cp.async.wait_group 0;");
    __syncthreads();

    uint32_t qh[4][4];
    #pragma unroll
    for (int ks = 0; ks < 4; ks++) {
        const int row = wq0 + (lane & 15);
        const int col = ks * 16 + (lane >> 4) * 8;
        ldm_x4(qh[ks], sb + (uint32_t)((row * APAD + col) * 2));
    }
    __syncthreads();

    auto load_kv = [&](int st, int kt) {
        const int rbase = b * Tt + kt * 64;
        #pragma unroll
        for (int i = 0; i < 4; i++) {
            const int t2 = tid + i * 128;
            const int row = t2 >> 3, seg = (t2 & 7) * 8;
            const size_t srcK = (size_t)(rbase + row) * QKV3 + Dd + colb + seg;
            const uint32_t dst = sb + (uint32_t)((st * ASTG + row * APAD + seg) * 2);
            cp16(dst,             qkv + srcK);        // K
            cp16(dst + ATILE * 2, qkv + srcK + Dd);   // V
        }
    };

    float oacc[8][4];
    #pragma unroll
    for (int i = 0; i < 8; i++)
        #pragma unroll
        for (int t = 0; t < 4; t++) oacc[i][t] = 0.f;
    float m0 = -1e30f, m1 = -1e30f, l0 = 0.f, l1 = 0.f;

    load_kv(0, 0);
    asm volatile("cp.async.commit_group;");

    const int r0 = lane >> 2, c0 = (lane & 3) * 2;

    for (int kt = 0; kt <= qt; kt++) {
        if (kt < qt) load_kv((kt + 1) & 1, kt + 1);
        asm volatile("cp.async.commit_group;");
        asm volatile("cp.async.wait_group 1;");
        __syncthreads();
        const uint32_t stb = sb + (uint32_t)((kt & 1) * ASTG * 2);

        float sacc[8][4];
        #pragma unroll
        for (int i = 0; i < 8; i++)
            #pragma unroll
            for (int t = 0; t < 4; t++) sacc[i][t] = 0.f;

        #pragma unroll
        for (int ks = 0; ks < 4; ks++) {
            #pragma unroll
            for (int np = 0; np < 4; np++) {
                const int row = np * 16 + ((lane >> 4) & 1) * 8 + (lane & 7);
                const int col = ks * 16 + ((lane >> 3) & 1) * 8;
                uint32_t rk[4];
                ldm_x4(rk, stb + (uint32_t)((row * APAD + col) * 2));
                uint32_t b0[2] = {rk[0], rk[1]}, b1[2] = {rk[2], rk[3]};
                mma16816(sacc[np * 2],     qh[ks], b0);
                mma16816(sacc[np * 2 + 1], qh[ks], b1);
            }
        }

        const bool diag = (kt == qt);
        #pragma unroll
        for (int nt = 0; nt < 8; nt++) {
            #pragma unroll
            for (int e = 0; e < 4; e++) {
                float sv = sacc[nt][e] * 0.125f;
                if (diag) {
                    const int rr = wq0 + r0 + ((e >> 1) << 3);
                    const int cc = nt * 8 + c0 + (e & 1);
                    if (cc > rr) sv = -1e30f;
                }
                sacc[nt][e] = sv;
            }
        }

        float mx0 = -1e30f, mx1 = -1e30f;
        #pragma unroll
        for (int nt = 0; nt < 8; nt++) {
            mx0 = fmaxf(mx0, fmaxf(sacc[nt][0], sacc[nt][1]));
            mx1 = fmaxf(mx1, fmaxf(sacc[nt][2], sacc[nt][3]));
        }
        mx0 = fmaxf(mx0, __shfl_xor_sync(0xffffffffu, mx0, 1));
        mx0 = fmaxf(mx0, __shfl_xor_sync(0xffffffffu, mx0, 2));
        mx1 = fmaxf(mx1, __shfl_xor_sync(0xffffffffu, mx1, 1));
        mx1 = fmaxf(mx1, __shfl_xor_sync(0xffffffffu, mx1, 2));
        const float mn0 = fmaxf(m0, mx0), mn1 = fmaxf(m1, mx1);
        const float sc0 = __expf(m0 - mn0), sc1 = __expf(m1 - mn1);
        m0 = mn0; m1 = mn1;

        uint32_t ph[4][4], pl[4][4];
        float s0 = 0.f, s1 = 0.f;
        #pragma unroll
        for (int nt = 0; nt < 8; nt++) {
            const float p0 = __expf(sacc[nt][0] - mn0);
            const float p1 = __expf(sacc[nt][1] - mn0);
            const float p2 = __expf(sacc[nt][2] - mn1);
            const float p3 = __expf(sacc[nt][3] - mn1);
            s0 += p0 + p1; s1 += p2 + p3;
            const float h0 = __bfloat162float(__float2bfloat16(p0));
            const float h1 = __bfloat162float(__float2bfloat16(p1));
            const float h2 = __bfloat162float(__float2bfloat16(p2));
            const float h3 = __bfloat162float(__float2bfloat16(p3));
            const int ks2 = nt >> 1, hf = (nt & 1) * 2;
            ph[ks2][hf]     = packbf(h0, h1);
            ph[ks2][hf + 1] = packbf(h2, h3);
            pl[ks2][hf]     = packbf(p0 - h0, p1 - h1);
            pl[ks2][hf + 1] = packbf(p2 - h2, p3 - h3);
        }
        s0 += __shfl_xor_sync(0xffffffffu, s0, 1);
        s0 += __shfl_xor_sync(0xffffffffu, s0, 2);
        s1 += __shfl_xor_sync(0xffffffffu, s1, 1);
        s1 += __shfl_xor_sync(0xffffffffu, s1, 2);
        l0 = l0 * sc0 + s0;
        l1 = l1 * sc1 + s1;

        #pragma unroll
        for (int dt = 0; dt < 8; dt++) {
            oacc[dt][0] *= sc0; oacc[dt][1] *= sc0;
            oacc[dt][2] *= sc1; oacc[dt][3] *= sc1;
        }

        const uint32_t vtb = stb + ATILE * 2;
        #pragma unroll
        for (int ks = 0; ks < 4; ks++) {
            #pragma unroll
            for (int dp = 0; dp < 4; dp++) {
                const int krow = 16 * ks + (lane & 15);
                const int ncol = dp * 16 + (lane >> 4) * 8;
                uint32_t rv[4];
                ldm_x4_t(rv, vtb + (uint32_t)((krow * APAD + ncol) * 2));
                uint32_t v0[2] = {rv[0], rv[1]}, v1[2] = {rv[2], rv[3]};
                mma16816(oacc[dp * 2],     ph[ks], v0);
                mma16816(oacc[dp * 2],     pl[ks], v0);
                mma16816(oacc[dp * 2 + 1], ph[ks], v1);
                mma16816(oacc[dp * 2 + 1], pl[ks], v1);
            }
        }
        __syncthreads();
    }

    const float inv0 = 1.f / l0, inv1 = 1.f / l1;
    const size_t rg0 = (size_t)(b * Tt + qt * 64 + wq0 + r0);
    #pragma unroll
    for (int dt = 0; dt < 8; dt++) {
        const int col = colb + dt * 8 + c0;
        {
            __nv_bfloat162 hp;
            hp.x = __float2bfloat16(oacc[dt][0] * inv0);
            hp.y = __float2bfloat16(oacc[dt][1] * inv0);
            *(__nv_bfloat162*)(ch + rg0 * Dd + col) = hp;
        }
        {
            __nv_bfloat162 hp;
            hp.x = __float2bfloat16(oacc[dt][2] * inv1);
            hp.y = __float2bfloat16(oacc[dt][3] * inv1);
            *(__nv_bfloat162*)(ch + (rg0 + 8) * Dd + col) = hp;
        }
    }
}

// ---------------------------------------------------------------------------
// Launch
// ---------------------------------------------------------------------------
extern "C" void kernel_launch(void* const* d_in, const int* in_sizes, int n_in,
                              void* d_out, int out_size)
{
    const float* x    = (const float*)d_in[0];
    const float* ln1s = (const float*)d_in[1];
    const float* ln1b = (const float*)d_in[2];
    const float* wq   = (const float*)d_in[3];
    const float* wk   = (const float*)d_in[4];
    const float* wv   = (const float*)d_in[5];
    const float* wo   = (const float*)d_in[6];
    const float* bo   = (const float*)d_in[7];
    const float* ln2s = (const float*)d_in[8];
    const float* ln2b = (const float*)d_in[9];
    const float* w1   = (const float*)d_in[10];
    const float* b1   = (const float*)d_in[11];
    const float* w2   = (const float*)d_in[12];
    const float* b2   = (const float*)d_in[13];
    float* out = (float*)d_out;

    float* x1;
    cudaGetSymbolAddress((void**)&x1, g_x1);

    __nv_bfloat16 *xn, *qkv, *ctx, *hbuf;
    __nv_bfloat16 *wqkvh, *wqkvl, *woh, *wol, *w1h, *w1l, *w2h, *w2l;
    cudaGetSymbolAddress((void**)&xn,    g_xn);
    cudaGetSymbolAddress((void**)&qkv,   g_qkv);
    cudaGetSymbolAddress((void**)&ctx,   g_ctx);
    cudaGetSymbolAddress((void**)&hbuf,  g_h);
    cudaGetSymbolAddress((void**)&wqkvh, g_wqkv_h);
    cudaGetSymbolAddress((void**)&wqkvl, g_wqkv_l);
    cudaGetSymbolAddress((void**)&woh,   g_wo_h);
    cudaGetSymbolAddress((void**)&wol,   g_wo_l);
    cudaGetSymbolAddress((void**)&w1h,   g_w1_h);
    cudaGetSymbolAddress((void**)&w1l,   g_w1_l);
    cudaGetSymbolAddress((void**)&w2h,   g_w2_h);
    cudaGetSymbolAddress((void**)&w2l,   g_w2_l);

    cudaFuncSetAttribute(attn_mma,
                         cudaFuncAttributeMaxDynamicSharedMemorySize, ATTN_SMEM2);
    cudaFuncSetAttribute(gemm_plain,
                         cudaFuncAttributeMaxDynamicSharedMemorySize, PSMEM_BYTES);
    cudaFuncSetAttribute(gemm_mma2<2>,
                         cudaFuncAttributeMaxDynamicSharedMemorySize, GSMEM_BYTES);
    cudaFuncSetAttribute(gemm_mma2<3>,
                         cudaFuncAttributeMaxDynamicSharedMemorySize, GSMEM_BYTES);

    // All weight conversions in one launch
    cvt_weights<<<(CVT_TOTAL + 255) / 256, 256>>>(
        wq, wk, wv, wo, w1, w2,
        wqkvh, wqkvl, woh, wol, w1h, w1l, w2h, w2l);

    // LN1 -> xn (bf16)
    ln_bf16<<<MROWS, 256>>>(x, ln1s, ln1b, xn);

    // Fused QKV projection, PLAIN bf16 -> qkv, N = 2304
    dim3 gqkv(QKV3 / 128, MROWS / 128);
    gemm_plain<<<gqkv, 256, PSMEM_BYTES>>>(xn, wqkvh, qkv, MROWS, QKV3, Dd);

    // Attention (HMMA flash) -> ctx (bf16)
    dim3 ga(Tt / 64, Hh, Bb);
    attn_mma<<<ga, 128, ATTN_SMEM2>>>(qkv, ctx);

    // O projection (2-term weight split) + bias + residual -> x1 (fp32)
    dim3 gdd(Dd / 128, MROWS / 128);
    gemm_mma2<2><<<gdd, 256, GSMEM_BYTES>>>(ctx, woh, wol, bo, x,
                                            x1, nullptr, MROWS, Dd, Dd);

    // LN2 -> xn (bf16)
    ln_bf16<<<MROWS, 256>>>(x1, ln2s, ln2b, xn);

    // MLP1: 2-term, bias + GELU -> h (bf16)
    dim3 g1(DFF / 128, MROWS / 128);
    gemm_mma2<3><<<g1, 256, GSMEM_BYTES>>>(xn, w1h, w1l, b1, nullptr,
                                           nullptr, hbuf, MROWS, DFF, Dd);

    // MLP2: 2-term, bias + residual -> out (fp32)
    gemm_mma2<2><<<gdd, 256, GSMEM_BYTES>>>(hbuf, w2h, w2l, b2, x1,
                                            out, nullptr, MROWS, Dd, DFF);
}

// round 16
// speedup vs baseline: 2.2233x; 1.3502x over previous
#include <cuda_runtime.h>
#include <cuda_fp16.h>
#include <math.h>
#include <cstdint>

// ---------------------------------------------------------------------------
// Problem constants
// ---------------------------------------------------------------------------
namespace {
constexpr int Bb   = 2;
constexpr int Tt   = 2048;
constexpr int Dd   = 768;
constexpr int QKV3 = 3 * Dd;       // 2304
constexpr int Hh   = 12;
constexpr int MROWS = Bb * Tt;     // 4096
constexpr int DFF   = 4 * Dd;      // 3072
constexpr int NDD  = Dd * Dd;      // 589824
constexpr int NW1  = DFF * Dd;     // 2359296
constexpr int CVT_TOTAL = 4 * NDD + 2 * NW1;  // 7077888

// GEMM tiling: CTA 128x128, BK=32, 2-stage cp.async pipeline, plain fp16
constexpr int AP   = 40;             // padded row length (fp16 elems), 80B
constexpr int TSZ  = 128 * AP;       // elems per tile: 5120
constexpr int PSTG = 2 * TSZ;        // per stage (A, B): 10240
constexpr int PSMEM_BYTES = 2 * PSTG * 2;  // 40960

// attention smem: 2 stages x (K, V) 64x72 fp16 tiles
constexpr int APAD = 72;
constexpr int ATILE = 64 * APAD;        // 4608 elems
constexpr int ASTG  = 2 * ATILE;        // 9216 elems per stage
constexpr int ATTN_SMEM2 = 2 * ASTG * 2;  // 36864 bytes
}

// ---------------------------------------------------------------------------
// Scratch (no allocation allowed)
// ---------------------------------------------------------------------------
__device__ float g_x1 [MROWS * Dd];

__device__ __half g_xn  [MROWS * Dd];
__device__ __half g_qkv [MROWS * QKV3];
__device__ __half g_ctx [MROWS * Dd];
__device__ __half g_h   [MROWS * DFF];
__device__ __half g_wqkv[QKV3 * Dd];
__device__ __half g_wo  [Dd * Dd];
__device__ __half g_w1  [DFF * Dd];
__device__ __half g_w2  [Dd * DFF];

// ---------------------------------------------------------------------------
// PTX helpers (baseline PTX, legal at compute_100)
// ---------------------------------------------------------------------------
__device__ __forceinline__ uint32_t smem_u32(const void* p) {
    uint32_t a;
    asm("{ .reg .u64 t; cvta.to.shared.u64 t, %1; cvt.u32.u64 %0, t; }"
        : "=r"(a) : "l"(p));
    return a;
}

__device__ __forceinline__ void cp16(uint32_t dst, const void* src) {
    asm volatile("cp.async.cg.shared.global [%0], [%1], 16;" :: "r"(dst), "l"(src));
}

__device__ __forceinline__ void ldm_x4(uint32_t* r, uint32_t addr) {
    asm volatile("ldmatrix.sync.aligned.m8n8.x4.shared.b16 {%0,%1,%2,%3}, [%4];"
        : "=r"(r[0]), "=r"(r[1]), "=r"(r[2]), "=r"(r[3]) : "r"(addr));
}

__device__ __forceinline__ void ldm_x4_t(uint32_t* r, uint32_t addr) {
    asm volatile("ldmatrix.sync.aligned.m8n8.x4.trans.shared.b16 {%0,%1,%2,%3}, [%4];"
        : "=r"(r[0]), "=r"(r[1]), "=r"(r[2]), "=r"(r[3]) : "r"(addr));
}

__device__ __forceinline__ void mma16816(float* c, const uint32_t* a, const uint32_t* b) {
    asm volatile(
        "mma.sync.aligned.m16n8k16.row.col.f32.f16.f16.f32 "
        "{%0,%1,%2,%3}, {%4,%5,%6,%7}, {%8,%9}, {%0,%1,%2,%3};"
        : "+f"(c[0]), "+f"(c[1]), "+f"(c[2]), "+f"(c[3])
        : "r"(a[0]), "r"(a[1]), "r"(a[2]), "r"(a[3]), "r"(b[0]), "r"(b[1]));
}

// pack two floats to half2 as u32
__device__ __forceinline__ uint32_t packh2(float lo, float hi) {
    const __half2 h = __floats2half2_rn(lo, hi);
    return *(const uint32_t*)&h;
}

// ---------------------------------------------------------------------------
// LayerNorm -> fp16
// ---------------------------------------------------------------------------
__global__ __launch_bounds__(256) void ln_f16(
    const float* __restrict__ x, const float* __restrict__ sc,
    const float* __restrict__ sh, __half* __restrict__ oh)
{
    const int row = blockIdx.x;
    const float* xr = x + (size_t)row * Dd;
    __shared__ float s1[256], s2[256];
    float a = 0.f, b = 0.f;
    for (int i = threadIdx.x; i < Dd; i += 256) {
        float v = xr[i];
        a += v; b += v * v;
    }
    s1[threadIdx.x] = a; s2[threadIdx.x] = b;
    __syncthreads();
    for (int off = 128; off > 0; off >>= 1) {
        if (threadIdx.x < off) {
            s1[threadIdx.x] += s1[threadIdx.x + off];
            s2[threadIdx.x] += s2[threadIdx.x + off];
        }
        __syncthreads();
    }
    const float mean = s1[0] * (1.f / Dd);
    const float var  = s2[0] * (1.f / Dd) - mean * mean;
    const float rstd = rsqrtf(var + 1e-5f);
    for (int i = threadIdx.x; i < Dd; i += 256) {
        const float v = sc[i] * (xr[i] - mean) * rstd + sh[i];
        oh[(size_t)row * Dd + i] = __float2half(v);
    }
}

// ---------------------------------------------------------------------------
// All six weight matrices -> fp16 in ONE launch.
// ---------------------------------------------------------------------------
__global__ __launch_bounds__(256) void cvt_weights(
    const float* __restrict__ wq, const float* __restrict__ wk,
    const float* __restrict__ wv, const float* __restrict__ wo,
    const float* __restrict__ w1, const float* __restrict__ w2,
    __half* __restrict__ wqkv, __half* __restrict__ woh,
    __half* __restrict__ w1h,  __half* __restrict__ w2h)
{
    const int gid = blockIdx.x * 256 + threadIdx.x;
    if (gid >= CVT_TOTAL) return;
    float v;
    __half* dh;
    if (gid < 3 * NDD) {
        v = (gid < NDD) ? wq[gid] : (gid < 2 * NDD) ? wk[gid - NDD] : wv[gid - 2 * NDD];
        dh = wqkv + gid;
    } else if (gid < 4 * NDD) {
        const int j = gid - 3 * NDD;
        v = wo[j]; dh = woh + j;
    } else if (gid < 4 * NDD + NW1) {
        const int j = gid - 4 * NDD;
        v = w1[j]; dh = w1h + j;
    } else {
        const int j = gid - 4 * NDD - NW1;
        v = w2[j]; dh = w2h + j;
    }
    *dh = __float2half(v);
}

// ---------------------------------------------------------------------------
// Plain fp16 NT GEMM: C = A * B^T
// EPI: 1 = fp16 out, no bias; 2 = +bias +res, fp32 out; 3 = +bias, GELU, fp16
// CTA 128x128, BK=32, 256 thr = 8 warps (2m x 4n), warp tile 64x32.
// ---------------------------------------------------------------------------
template<int EPI>
__global__ __launch_bounds__(256, 2) void gemm_f16(
    const __half* __restrict__ A, const __half* __restrict__ B,
    const float* __restrict__ bias, const float* __restrict__ res,
    float* __restrict__ Cf, __half* __restrict__ Ch,
    int M, int N, int K)
{
    extern __shared__ __align__(16) char smem[];
    const uint32_t sb = smem_u32(smem);
    const int tid  = threadIdx.x;
    const int lane = tid & 31;
    const int w    = tid >> 5;
    const int wm   = w & 1;
    const int wn   = w >> 1;
    const int m0   = blockIdx.y * 128, n0 = blockIdx.x * 128;

    float acc[4][4][4];
    #pragma unroll
    for (int mi = 0; mi < 4; mi++)
        #pragma unroll
        for (int ni = 0; ni < 4; ni++)
            #pragma unroll
            for (int t = 0; t < 4; t++) acc[mi][ni][t] = 0.f;

    const int nc = K >> 5;

    auto load_stage = [&](int st, int c) {
        const int k0 = c << 5;
        const uint32_t stb = sb + (uint32_t)(st * PSTG * 2);
        #pragma unroll
        for (int i = 0; i < 2; i++) {
            const int id  = tid + i * 256;
            const int row = id >> 2, seg = id & 3;
            const uint32_t d = (uint32_t)((row * AP + seg * 8) * 2);
            cp16(stb + d,           A + (size_t)(m0 + row) * K + k0 + seg * 8);
            cp16(stb + TSZ * 2 + d, B + (size_t)(n0 + row) * K + k0 + seg * 8);
        }
    };

    load_stage(0, 0);
    asm volatile("cp.async.commit_group;");

    for (int c = 0; c < nc; c++) {
        if (c + 1 < nc) load_stage((c + 1) & 1, c + 1);
        asm volatile("cp.async.commit_group;");
        asm volatile("cp.async.wait_group 1;");
        __syncthreads();

        const uint32_t stb = sb + (uint32_t)((c & 1) * PSTG * 2);
        #pragma unroll
        for (int ks = 0; ks < 2; ks++) {
            uint32_t bb[4][2];
            #pragma unroll
            for (int np = 0; np < 2; np++) {
                const int row = wn * 32 + np * 16 + ((lane >> 4) & 1) * 8 + (lane & 7);
                const int col = ks * 16 + ((lane >> 3) & 1) * 8;
                uint32_t r[4];
                ldm_x4(r, stb + TSZ * 2 + (uint32_t)((row * AP + col) * 2));
                bb[np * 2][0] = r[0]; bb[np * 2][1] = r[1];
                bb[np * 2 + 1][0] = r[2]; bb[np * 2 + 1][1] = r[3];
            }
            #pragma unroll
            for (int mi = 0; mi < 4; mi++) {
                const int row = wm * 64 + mi * 16 + (lane & 15);
                const int col = ks * 16 + (lane >> 4) * 8;
                uint32_t aa[4];
                ldm_x4(aa, stb + (uint32_t)((row * AP + col) * 2));
                #pragma unroll
                for (int ni = 0; ni < 4; ni++)
                    mma16816(acc[mi][ni], aa, bb[ni]);
            }
        }
        __syncthreads();
    }

    // --- epilogue ---
    const int rbase = m0 + wm * 64 + (lane >> 2);
    const int cbase = n0 + wn * 32 + (lane & 3) * 2;
    #pragma unroll
    for (int mi = 0; mi < 4; mi++) {
        #pragma unroll
        for (int ni = 0; ni < 4; ni++) {
            #pragma unroll
            for (int half = 0; half < 2; half++) {
                const int m = rbase + mi * 16 + half * 8;
                const int n = cbase + ni * 8;
                float v0 = acc[mi][ni][half * 2];
                float v1 = acc[mi][ni][half * 2 + 1];
                const size_t o = (size_t)m * N + n;
                if (EPI == 1) {
                    const __half2 hp = __floats2half2_rn(v0, v1);
                    *(__half2*)(Ch + o) = hp;
                } else if (EPI == 2) {
                    const float2 r2 = *(const float2*)(res + o);
                    float2 t = {v0 + bias[n] + r2.x, v1 + bias[n + 1] + r2.y};
                    *(float2*)(Cf + o) = t;
                } else {  // EPI == 3: bias + GELU -> fp16
                    float u0 = v0 + bias[n];
                    float u1 = v1 + bias[n + 1];
                    const float i0 = 0.7978845608028654f * (u0 + 0.044715f * u0 * u0 * u0);
                    const float i1 = 0.7978845608028654f * (u1 + 0.044715f * u1 * u1 * u1);
                    const float g0 = 0.5f * u0 * (1.f + tanhf(i0));
                    const float g1 = 0.5f * u1 * (1.f + tanhf(i1));
                    const __half2 hp = __floats2half2_rn(g0, g1);
                    *(__half2*)(Ch + o) = hp;
                }
            }
        }
    }
}

// ---------------------------------------------------------------------------
// HMMA fp16 causal flash attention. fp16 Q/K/V/P, fp32 softmax + accum.
// Grid (32, 12, 2), 128 threads, forced 4 CTAs/SM.
// ---------------------------------------------------------------------------
__global__ __launch_bounds__(128, 4) void attn_mma(
    const __half* __restrict__ qkv, __half* __restrict__ ch)
{
    extern __shared__ __align__(16) char smem[];
    const uint32_t sb = smem_u32(smem);
    const int tid = threadIdx.x, lane = tid & 31, w = tid >> 5;
    const int qt = (int)gridDim.x - 1 - (int)blockIdx.x;
    const int h = blockIdx.y, b = blockIdx.z;
    const int wq0 = w * 16;
    const int colb = h * 64;

    {
        const int rbase = b * Tt + qt * 64;
        #pragma unroll
        for (int i = 0; i < 4; i++) {
            const int t2 = tid + i * 128;
            const int row = t2 >> 3, seg = (t2 & 7) * 8;
            const size_t src = (size_t)(rbase + row) * QKV3 + colb + seg;
            cp16(sb + (uint32_t)((row * APAD + seg) * 2), qkv + src);
        }
    }
    asm volatile("cp.async.commit_group;");
    asm volatile("cp.async.wait_group 0;");
    __syncthreads();

    uint32_t qh[4][4];
    #pragma unroll
    for (int ks = 0; ks < 4; ks++) {
        const int row = wq0 + (lane & 15);
        const int col = ks * 16 + (lane >> 4) * 8;
        ldm_x4(qh[ks], sb + (uint32_t)((row * APAD + col) * 2));
    }
    __syncthreads();

    auto load_kv = [&](int st, int kt) {
        const int rbase = b * Tt + kt * 64;
        #pragma unroll
        for (int i = 0; i < 4; i++) {
            const int t2 = tid + i * 128;
            const int row = t2 >> 3, seg = (t2 & 7) * 8;
            const size_t srcK = (size_t)(rbase + row) * QKV3 + Dd + colb + seg;
            const uint32_t dst = sb + (uint32_t)((st * ASTG + row * APAD + seg) * 2);
            cp16(dst,             qkv + srcK);        // K
            cp16(dst + ATILE * 2, qkv + srcK + Dd);   // V
        }
    };

    float oacc[8][4];
    #pragma unroll
    for (int i = 0; i < 8; i++)
        #pragma unroll
        for (int t = 0; t < 4; t++) oacc[i][t] = 0.f;
    float m0 = -1e30f, m1 = -1e30f, l0 = 0.f, l1 = 0.f;

    load_kv(0, 0);
    asm volatile("cp.async.commit_group;");

    const int r0 = lane >> 2, c0 = (lane & 3) * 2;

    for (int kt = 0; kt <= qt; kt++) {
        if (kt < qt) load_kv((kt + 1) & 1, kt + 1);
        asm volatile("cp.async.commit_group;");
        asm volatile("cp.async.wait_group 1;");
        __syncthreads();
        const uint32_t stb = sb + (uint32_t)((kt & 1) * ASTG * 2);

        float sacc[8][4];
        #pragma unroll
        for (int i = 0; i < 8; i++)
            #pragma unroll
            for (int t = 0; t < 4; t++) sacc[i][t] = 0.f;

        #pragma unroll
        for (int ks = 0; ks < 4; ks++) {
            #pragma unroll
            for (int np = 0; np < 4; np++) {
                const int row = np * 16 + ((lane >> 4) & 1) * 8 + (lane & 7);
                const int col = ks * 16 + ((lane >> 3) & 1) * 8;
                uint32_t rk[4];
                ldm_x4(rk, stb + (uint32_t)((row * APAD + col) * 2));
                uint32_t b0[2] = {rk[0], rk[1]}, b1[2] = {rk[2], rk[3]};
                mma16816(sacc[np * 2],     qh[ks], b0);
                mma16816(sacc[np * 2 + 1], qh[ks], b1);
            }
        }

        const bool diag = (kt == qt);
        #pragma unroll
        for (int nt = 0; nt < 8; nt++) {
            #pragma unroll
            for (int e = 0; e < 4; e++) {
                float sv = sacc[nt][e] * 0.125f;
                if (diag) {
                    const int rr = wq0 + r0 + ((e >> 1) << 3);
                    const int cc = nt * 8 + c0 + (e & 1);
                    if (cc > rr) sv = -1e30f;
                }
                sacc[nt][e] = sv;
            }
        }

        float mx0 = -1e30f, mx1 = -1e30f;
        #pragma unroll
        for (int nt = 0; nt < 8; nt++) {
            mx0 = fmaxf(mx0, fmaxf(sacc[nt][0], sacc[nt][1]));
            mx1 = fmaxf(mx1, fmaxf(sacc[nt][2], sacc[nt][3]));
        }
        mx0 = fmaxf(mx0, __shfl_xor_sync(0xffffffffu, mx0, 1));
        mx0 = fmaxf(mx0, __shfl_xor_sync(0xffffffffu, mx0, 2));
        mx1 = fmaxf(mx1, __shfl_xor_sync(0xffffffffu, mx1, 1));
        mx1 = fmaxf(mx1, __shfl_xor_sync(0xffffffffu, mx1, 2));
        const float mn0 = fmaxf(m0, mx0), mn1 = fmaxf(m1, mx1);
        const float sc0 = __expf(m0 - mn0), sc1 = __expf(m1 - mn1);
        m0 = mn0; m1 = mn1;

        uint32_t ph[4][4];
        float s0 = 0.f, s1 = 0.f;
        #pragma unroll
        for (int nt = 0; nt < 8; nt++) {
            const float p0 = __expf(sacc[nt][0] - mn0);
            const float p1 = __expf(sacc[nt][1] - mn0);
            const float p2 = __expf(sacc[nt][2] - mn1);
            const float p3 = __expf(sacc[nt][3] - mn1);
            s0 += p0 + p1; s1 += p2 + p3;
            const int ks2 = nt >> 1, hf = (nt & 1) * 2;
            ph[ks2][hf]     = packh2(p0, p1);
            ph[ks2][hf + 1] = packh2(p2, p3);
        }
        s0 += __shfl_xor_sync(0xffffffffu, s0, 1);
        s0 += __shfl_xor_sync(0xffffffffu, s0, 2);
        s1 += __shfl_xor_sync(0xffffffffu, s1, 1);
        s1 += __shfl_xor_sync(0xffffffffu, s1, 2);
        l0 = l0 * sc0 + s0;
        l1 = l1 * sc1 + s1;

        #pragma unroll
        for (int dt = 0; dt < 8; dt++) {
            oacc[dt][0] *= sc0; oacc[dt][1] *= sc0;
            oacc[dt][2] *= sc1; oacc[dt][3] *= sc1;
        }

        const uint32_t vtb = stb + ATILE * 2;
        #pragma unroll
        for (int ks = 0; ks < 4; ks++) {
            #pragma unroll
            for (int dp = 0; dp < 4; dp++) {
                const int krow = 16 * ks + (lane & 15);
                const int ncol = dp * 16 + (lane >> 4) * 8;
                uint32_t rv[4];
                ldm_x4_t(rv, vtb + (uint32_t)((krow * APAD + ncol) * 2));
                uint32_t v0[2] = {rv[0], rv[1]}, v1[2] = {rv[2], rv[3]};
                mma16816(oacc[dp * 2],     ph[ks], v0);
                mma16816(oacc[dp * 2 + 1], ph[ks], v1);
            }
        }
        __syncthreads();
    }

    const float inv0 = 1.f / l0, inv1 = 1.f / l1;
    const size_t rg0 = (size_t)(b * Tt + qt * 64 + wq0 + r0);
    #pragma unroll
    for (int dt = 0; dt < 8; dt++) {
        const int col = colb + dt * 8 + c0;
        {
            const __half2 hp = __floats2half2_rn(oacc[dt][0] * inv0, oacc[dt][1] * inv0);
            *(__half2*)(ch + rg0 * Dd + col) = hp;
        }
        {
            const __half2 hp = __floats2half2_rn(oacc[dt][2] * inv1, oacc[dt][3] * inv1);
            *(__half2*)(ch + (rg0 + 8) * Dd + col) = hp;
        }
    }
}

// ---------------------------------------------------------------------------
// Launch
// ---------------------------------------------------------------------------
extern "C" void kernel_launch(void* const* d_in, const int* in_sizes, int n_in,
                              void* d_out, int out_size)
{
    const float* x    = (const float*)d_in[0];
    const float* ln1s = (const float*)d_in[1];
    const float* ln1b = (const float*)d_in[2];
    const float* wq   = (const float*)d_in[3];
    const float* wk   = (const float*)d_in[4];
    const float* wv   = (const float*)d_in[5];
    const float* wo   = (const float*)d_in[6];
    const float* bo   = (const float*)d_in[7];
    const float* ln2s = (const float*)d_in[8];
    const float* ln2b = (const float*)d_in[9];
    const float* w1   = (const float*)d_in[10];
    const float* b1   = (const float*)d_in[11];
    const float* w2   = (const float*)d_in[12];
    const float* b2   = (const float*)d_in[13];
    float* out = (float*)d_out;

    float* x1;
    cudaGetSymbolAddress((void**)&x1, g_x1);

    __half *xn, *qkv, *ctx, *hbuf, *wqkv, *woh, *w1h, *w2h;
    cudaGetSymbolAddress((void**)&xn,   g_xn);
    cudaGetSymbolAddress((void**)&qkv,  g_qkv);
    cudaGetSymbolAddress((void**)&ctx,  g_ctx);
    cudaGetSymbolAddress((void**)&hbuf, g_h);
    cudaGetSymbolAddress((void**)&wqkv, g_wqkv);
    cudaGetSymbolAddress((void**)&woh,  g_wo);
    cudaGetSymbolAddress((void**)&w1h,  g_w1);
    cudaGetSymbolAddress((void**)&w2h,  g_w2);

    cudaFuncSetAttribute(attn_mma,
                         cudaFuncAttributeMaxDynamicSharedMemorySize, ATTN_SMEM2);
    cudaFuncSetAttribute(gemm_f16<1>,
                         cudaFuncAttributeMaxDynamicSharedMemorySize, PSMEM_BYTES);
    cudaFuncSetAttribute(gemm_f16<2>,
                         cudaFuncAttributeMaxDynamicSharedMemorySize, PSMEM_BYTES);
    cudaFuncSetAttribute(gemm_f16<3>,
                         cudaFuncAttributeMaxDynamicSharedMemorySize, PSMEM_BYTES);

    // All weight conversions in one launch
    cvt_weights<<<(CVT_TOTAL + 255) / 256, 256>>>(
        wq, wk, wv, wo, w1, w2, wqkv, woh, w1h, w2h);

    // LN1 -> xn (fp16)
    ln_f16<<<MROWS, 256>>>(x, ln1s, ln1b, xn);

    // Fused QKV projection -> qkv (fp16), N = 2304
    dim3 gqkv(QKV3 / 128, MROWS / 128);
    gemm_f16<1><<<gqkv, 256, PSMEM_BYTES>>>(xn, wqkv, nullptr, nullptr,
                                            nullptr, qkv, MROWS, QKV3, Dd);

    // Attention (HMMA flash) -> ctx (fp16)
    dim3 ga(Tt / 64, Hh, Bb);
    attn_mma<<<ga, 128, ATTN_SMEM2>>>(qkv, ctx);

    // O projection + bias + residual -> x1 (fp32)
    dim3 gdd(Dd / 128, MROWS / 128);
    gemm_f16<2><<<gdd, 256, PSMEM_BYTES>>>(ctx, woh, bo, x,
                                           x1, nullptr, MROWS, Dd, Dd);

    // LN2 -> xn (fp16)
    ln_f16<<<MROWS, 256>>>(x1, ln2s, ln2b, xn);

    // MLP1: bias + GELU -> h (fp16)
    dim3 g1(DFF / 128, MROWS / 128);
    gemm_f16<3><<<g1, 256, PSMEM_BYTES>>>(xn, w1h, b1, nullptr,
                                          nullptr, hbuf, MROWS, DFF, Dd);

    // MLP2: bias + residual -> out (fp32)
    gemm_f16<2><<<gdd, 256, PSMEM_BYTES>>>(hbuf, w2h, b2, x1,
                                           out, nullptr, MROWS, Dd, DFF);
}

// round 17
// speedup vs baseline: 2.3497x; 1.0568x over previous
#include <cuda_runtime.h>
#include <cuda_fp16.h>
#include <math.h>
#include <cstdint>

// ---------------------------------------------------------------------------
// Problem constants
// ---------------------------------------------------------------------------
namespace {
constexpr int Bb   = 2;
constexpr int Tt   = 2048;
constexpr int Dd   = 768;
constexpr int QKV3 = 3 * Dd;       // 2304
constexpr int Hh   = 12;
constexpr int MROWS = Bb * Tt;     // 4096
constexpr int DFF   = 4 * Dd;      // 3072
constexpr int NDD  = Dd * Dd;      // 589824
constexpr int NW1  = DFF * Dd;     // 2359296
constexpr int CVT_TOTAL = 4 * NDD + 2 * NW1;  // 7077888

// GEMM tiling: CTA 128x128, BK=32, 3-stage cp.async pipeline, plain fp16
constexpr int AP   = 40;             // padded row length (fp16 elems), 80B
constexpr int TSZ  = 128 * AP;       // elems per tile: 5120
constexpr int PSTG = 2 * TSZ;        // per stage (A, B): 10240
constexpr int PSMEM_BYTES = 3 * PSTG * 2;  // 61440

// attention smem: 2 stages x (K, V) 64x72 fp16 tiles
constexpr int APAD = 72;
constexpr int ATILE = 64 * APAD;        // 4608 elems
constexpr int ASTG  = 2 * ATILE;        // 9216 elems per stage
constexpr int ATTN_SMEM2 = 2 * ASTG * 2;  // 36864 bytes
}

// ---------------------------------------------------------------------------
// Scratch (no allocation allowed)
// ---------------------------------------------------------------------------
__device__ float g_x1 [MROWS * Dd];

__device__ __half g_xn  [MROWS * Dd];
__device__ __half g_qkv [MROWS * QKV3];
__device__ __half g_ctx [MROWS * Dd];
__device__ __half g_h   [MROWS * DFF];
__device__ __half g_wqkv[QKV3 * Dd];
__device__ __half g_wo  [Dd * Dd];
__device__ __half g_w1  [DFF * Dd];
__device__ __half g_w2  [Dd * DFF];

// ---------------------------------------------------------------------------
// PTX helpers (baseline PTX, legal at compute_100)
// ---------------------------------------------------------------------------
__device__ __forceinline__ uint32_t smem_u32(const void* p) {
    uint32_t a;
    asm("{ .reg .u64 t; cvta.to.shared.u64 t, %1; cvt.u32.u64 %0, t; }"
        : "=r"(a) : "l"(p));
    return a;
}

__device__ __forceinline__ void cp16(uint32_t dst, const void* src) {
    asm volatile("cp.async.cg.shared.global [%0], [%1], 16;" :: "r"(dst), "l"(src));
}

__device__ __forceinline__ void ldm_x4(uint32_t* r, uint32_t addr) {
    asm volatile("ldmatrix.sync.aligned.m8n8.x4.shared.b16 {%0,%1,%2,%3}, [%4];"
        : "=r"(r[0]), "=r"(r[1]), "=r"(r[2]), "=r"(r[3]) : "r"(addr));
}

__device__ __forceinline__ void ldm_x4_t(uint32_t* r, uint32_t addr) {
    asm volatile("ldmatrix.sync.aligned.m8n8.x4.trans.shared.b16 {%0,%1,%2,%3}, [%4];"
        : "=r"(r[0]), "=r"(r[1]), "=r"(r[2]), "=r"(r[3]) : "r"(addr));
}

__device__ __forceinline__ void mma16816(float* c, const uint32_t* a, const uint32_t* b) {
    asm volatile(
        "mma.sync.aligned.m16n8k16.row.col.f32.f16.f16.f32 "
        "{%0,%1,%2,%3}, {%4,%5,%6,%7}, {%8,%9}, {%0,%1,%2,%3};"
        : "+f"(c[0]), "+f"(c[1]), "+f"(c[2]), "+f"(c[3])
        : "r"(a[0]), "r"(a[1]), "r"(a[2]), "r"(a[3]), "r"(b[0]), "r"(b[1]));
}

// pack two floats to half2 as u32
__device__ __forceinline__ uint32_t packh2(float lo, float hi) {
    const __half2 h = __floats2half2_rn(lo, hi);
    return *(const uint32_t*)&h;
}

// ---------------------------------------------------------------------------
// LayerNorm -> fp16
// ---------------------------------------------------------------------------
__global__ __launch_bounds__(256) void ln_f16(
    const float* __restrict__ x, const float* __restrict__ sc,
    const float* __restrict__ sh, __half* __restrict__ oh)
{
    const int row = blockIdx.x;
    const float* xr = x + (size_t)row * Dd;
    __shared__ float s1[256], s2[256];
    float a = 0.f, b = 0.f;
    for (int i = threadIdx.x; i < Dd; i += 256) {
        float v = xr[i];
        a += v; b += v * v;
    }
    s1[threadIdx.x] = a; s2[threadIdx.x] = b;
    __syncthreads();
    for (int off = 128; off > 0; off >>= 1) {
        if (threadIdx.x < off) {
            s1[threadIdx.x] += s1[threadIdx.x + off];
            s2[threadIdx.x] += s2[threadIdx.x + off];
        }
        __syncthreads();
    }
    const float mean = s1[0] * (1.f / Dd);
    const float var  = s2[0] * (1.f / Dd) - mean * mean;
    const float rstd = rsqrtf(var + 1e-5f);
    for (int i = threadIdx.x; i < Dd; i += 256) {
        const float v = sc[i] * (xr[i] - mean) * rstd + sh[i];
        oh[(size_t)row * Dd + i] = __float2half(v);
    }
}

// ---------------------------------------------------------------------------
// All six weight matrices -> fp16 in ONE launch.
// ---------------------------------------------------------------------------
__global__ __launch_bounds__(256) void cvt_weights(
    const float* __restrict__ wq, const float* __restrict__ wk,
    const float* __restrict__ wv, const float* __restrict__ wo,
    const float* __restrict__ w1, const float* __restrict__ w2,
    __half* __restrict__ wqkv, __half* __restrict__ woh,
    __half* __restrict__ w1h,  __half* __restrict__ w2h)
{
    const int gid = blockIdx.x * 256 + threadIdx.x;
    if (gid >= CVT_TOTAL) return;
    float v;
    __half* dh;
    if (gid < 3 * NDD) {
        v = (gid < NDD) ? wq[gid] : (gid < 2 * NDD) ? wk[gid - NDD] : wv[gid - 2 * NDD];
        dh = wqkv + gid;
    } else if (gid < 4 * NDD) {
        const int j = gid - 3 * NDD;
        v = wo[j]; dh = woh + j;
    } else if (gid < 4 * NDD + NW1) {
        const int j = gid - 4 * NDD;
        v = w1[j]; dh = w1h + j;
    } else {
        const int j = gid - 4 * NDD - NW1;
        v = w2[j]; dh = w2h + j;
    }
    *dh = __float2half(v);
}

// ---------------------------------------------------------------------------
// Plain fp16 NT GEMM: C = A * B^T, 3-stage pipeline, single sync per chunk.
// EPI: 1 = fp16 out, no bias; 2 = +bias +res, fp32 out; 3 = +bias, GELU, fp16
// CTA 128x128, BK=32, 256 thr = 8 warps (2m x 4n), warp tile 64x32.
// ---------------------------------------------------------------------------
template<int EPI>
__global__ __launch_bounds__(256, 2) void gemm_f16(
    const __half* __restrict__ A, const __half* __restrict__ B,
    const float* __restrict__ bias, const float* __restrict__ res,
    float* __restrict__ Cf, __half* __restrict__ Ch,
    int M, int N, int K)
{
    extern __shared__ __align__(16) char smem[];
    const uint32_t sb = smem_u32(smem);
    const int tid  = threadIdx.x;
    const int lane = tid & 31;
    const int w    = tid >> 5;
    const int wm   = w & 1;
    const int wn   = w >> 1;
    const int m0   = blockIdx.y * 128, n0 = blockIdx.x * 128;

    float acc[4][4][4];
    #pragma unroll
    for (int mi = 0; mi < 4; mi++)
        #pragma unroll
        for (int ni = 0; ni < 4; ni++)
            #pragma unroll
            for (int t = 0; t < 4; t++) acc[mi][ni][t] = 0.f;

    const int nc = K >> 5;   // >= 24 for all our shapes

    auto load_stage = [&](int st, int c) {
        const int k0 = c << 5;
        const uint32_t stb = sb + (uint32_t)(st * PSTG * 2);
        #pragma unroll
        for (int i = 0; i < 2; i++) {
            const int id  = tid + i * 256;
            const int row = id >> 2, seg = id & 3;
            const uint32_t d = (uint32_t)((row * AP + seg * 8) * 2);
            cp16(stb + d,           A + (size_t)(m0 + row) * K + k0 + seg * 8);
            cp16(stb + TSZ * 2 + d, B + (size_t)(n0 + row) * K + k0 + seg * 8);
        }
    };

    load_stage(0, 0);
    asm volatile("cp.async.commit_group;");
    load_stage(1, 1);
    asm volatile("cp.async.commit_group;");

    int st = 0;
    for (int c = 0; c < nc; c++) {
        asm volatile("cp.async.wait_group 1;");
        __syncthreads();

        const uint32_t stb = sb + (uint32_t)(st * PSTG * 2);
        #pragma unroll
        for (int ks = 0; ks < 2; ks++) {
            uint32_t bb[4][2];
            #pragma unroll
            for (int np = 0; np < 2; np++) {
                const int row = wn * 32 + np * 16 + ((lane >> 4) & 1) * 8 + (lane & 7);
                const int col = ks * 16 + ((lane >> 3) & 1) * 8;
                uint32_t r[4];
                ldm_x4(r, stb + TSZ * 2 + (uint32_t)((row * AP + col) * 2));
                bb[np * 2][0] = r[0]; bb[np * 2][1] = r[1];
                bb[np * 2 + 1][0] = r[2]; bb[np * 2 + 1][1] = r[3];
            }
            #pragma unroll
            for (int mi = 0; mi < 4; mi++) {
                const int row = wm * 64 + mi * 16 + (lane & 15);
                const int col = ks * 16 + (lane >> 4) * 8;
                uint32_t aa[4];
                ldm_x4(aa, stb + (uint32_t)((row * AP + col) * 2));
                #pragma unroll
                for (int ni = 0; ni < 4; ni++)
                    mma16816(acc[mi][ni], aa, bb[ni]);
            }
        }

        if (c + 2 < nc) {
            int st2 = st + 2;
            if (st2 >= 3) st2 -= 3;
            load_stage(st2, c + 2);
        }
        asm volatile("cp.async.commit_group;");
        if (++st == 3) st = 0;
    }

    // --- epilogue ---
    const int rbase = m0 + wm * 64 + (lane >> 2);
    const int cbase = n0 + wn * 32 + (lane & 3) * 2;
    #pragma unroll
    for (int mi = 0; mi < 4; mi++) {
        #pragma unroll
        for (int ni = 0; ni < 4; ni++) {
            #pragma unroll
            for (int half = 0; half < 2; half++) {
                const int m = rbase + mi * 16 + half * 8;
                const int n = cbase + ni * 8;
                float v0 = acc[mi][ni][half * 2];
                float v1 = acc[mi][ni][half * 2 + 1];
                const size_t o = (size_t)m * N + n;
                if (EPI == 1) {
                    const __half2 hp = __floats2half2_rn(v0, v1);
                    *(__half2*)(Ch + o) = hp;
                } else if (EPI == 2) {
                    const float2 r2 = *(const float2*)(res + o);
                    float2 t = {v0 + bias[n] + r2.x, v1 + bias[n + 1] + r2.y};
                    *(float2*)(Cf + o) = t;
                } else {  // EPI == 3: bias + GELU -> fp16
                    float u0 = v0 + bias[n];
                    float u1 = v1 + bias[n + 1];
                    const float i0 = 0.7978845608028654f * (u0 + 0.044715f * u0 * u0 * u0);
                    const float i1 = 0.7978845608028654f * (u1 + 0.044715f * u1 * u1 * u1);
                    const float g0 = 0.5f * u0 * (1.f + tanhf(i0));
                    const float g1 = 0.5f * u1 * (1.f + tanhf(i1));
                    const __half2 hp = __floats2half2_rn(g0, g1);
                    *(__half2*)(Ch + o) = hp;
                }
            }
        }
    }
}

// ---------------------------------------------------------------------------
// HMMA fp16 causal flash attention, 128-row q-tile.
// Grid (16, 12, 2), 256 threads (8 warps x 16 q-rows), 2 CTAs/SM.
// ---------------------------------------------------------------------------
__global__ __launch_bounds__(256, 2) void attn_mma(
    const __half* __restrict__ qkv, __half* __restrict__ ch)
{
    extern __shared__ __align__(16) char smem[];
    const uint32_t sb = smem_u32(smem);
    const int tid = threadIdx.x, lane = tid & 31, w = tid >> 5;
    const int qt = (int)gridDim.x - 1 - (int)blockIdx.x;   // heavy tiles first
    const int h = blockIdx.y, b = blockIdx.z;
    const int wq0 = w * 16;               // warp q-row offset within 128-row tile
    const int colb = h * 64;
    const int qrow0 = qt * 128;           // global q-row base

    // ---- stage Q (128x64) into stage0 (K+V areas), extract fragments ----
    {
        const int rbase = b * Tt + qrow0;
        #pragma unroll
        for (int i = 0; i < 4; i++) {
            const int t2 = tid + i * 256;          // 0..1023
            const int row = t2 >> 3, seg = (t2 & 7) * 8;
            const size_t src = (size_t)(rbase + row) * QKV3 + colb + seg;
            cp16(sb + (uint32_t)((row * APAD + seg) * 2), qkv + src);
        }
    }
    asm volatile("cp.async.commit_group;");
    asm volatile("cp.async.wait_group 0;");
    __syncthreads();

    uint32_t qh[4][4];
    #pragma unroll
    for (int ks = 0; ks < 4; ks++) {
        const int row = wq0 + (lane & 15);
        const int col = ks * 16 + (lane >> 4) * 8;
        ldm_x4(qh[ks], sb + (uint32_t)((row * APAD + col) * 2));
    }
    __syncthreads();

    auto load_kv = [&](int st, int kt) {
        const int rbase = b * Tt + kt * 64;
        #pragma unroll
        for (int i = 0; i < 2; i++) {
            const int t2 = tid + i * 256;          // 0..511
            const int row = t2 >> 3, seg = (t2 & 7) * 8;
            const size_t srcK = (size_t)(rbase + row) * QKV3 + Dd + colb + seg;
            const uint32_t dst = sb + (uint32_t)((st * ASTG + row * APAD + seg) * 2);
            cp16(dst,             qkv + srcK);        // K
            cp16(dst + ATILE * 2, qkv + srcK + Dd);   // V
        }
    };

    float oacc[8][4];
    #pragma unroll
    for (int i = 0; i < 8; i++)
        #pragma unroll
        for (int t = 0; t < 4; t++) oacc[i][t] = 0.f;
    float m0 = -1e30f, m1 = -1e30f, l0 = 0.f, l1 = 0.f;

    load_kv(0, 0);
    asm volatile("cp.async.commit_group;");

    const int r0 = lane >> 2, c0 = (lane & 3) * 2;
    const int nkt = 2 * qt + 2;           // key tiles: 0 .. 2qt+1

    for (int kt = 0; kt < nkt; kt++) {
        if (kt + 1 < nkt) load_kv((kt + 1) & 1, kt + 1);
        asm volatile("cp.async.commit_group;");
        asm volatile("cp.async.wait_group 1;");
        __syncthreads();
        const uint32_t stb = sb + (uint32_t)((kt & 1) * ASTG * 2);

        // ---- S = Q K^T ----
        float sacc[8][4];
        #pragma unroll
        for (int i = 0; i < 8; i++)
            #pragma unroll
            for (int t = 0; t < 4; t++) sacc[i][t] = 0.f;

        #pragma unroll
        for (int ks = 0; ks < 4; ks++) {
            #pragma unroll
            for (int np = 0; np < 4; np++) {
                const int row = np * 16 + ((lane >> 4) & 1) * 8 + (lane & 7);
                const int col = ks * 16 + ((lane >> 3) & 1) * 8;
                uint32_t rk[4];
                ldm_x4(rk, stb + (uint32_t)((row * APAD + col) * 2));
                uint32_t b0[2] = {rk[0], rk[1]}, b1[2] = {rk[2], rk[3]};
                mma16816(sacc[np * 2],     qh[ks], b0);
                mma16816(sacc[np * 2 + 1], qh[ks], b1);
            }
        }

        // ---- scale + causal mask (global indices) ----
        const bool needmask = (kt * 64 + 63 > qrow0 + wq0);
        #pragma unroll
        for (int nt = 0; nt < 8; nt++) {
            #pragma unroll
            for (int e = 0; e < 4; e++) {
                float sv = sacc[nt][e] * 0.125f;
                if (needmask) {
                    const int rr = qrow0 + wq0 + r0 + ((e >> 1) << 3);
                    const int cc = kt * 64 + nt * 8 + c0 + (e & 1);
                    if (cc > rr) sv = -1e30f;
                }
                sacc[nt][e] = sv;
            }
        }

        // ---- online softmax (row stats via quad shfl) ----
        float mx0 = -1e30f, mx1 = -1e30f;
        #pragma unroll
        for (int nt = 0; nt < 8; nt++) {
            mx0 = fmaxf(mx0, fmaxf(sacc[nt][0], sacc[nt][1]));
            mx1 = fmaxf(mx1, fmaxf(sacc[nt][2], sacc[nt][3]));
        }
        mx0 = fmaxf(mx0, __shfl_xor_sync(0xffffffffu, mx0, 1));
        mx0 = fmaxf(mx0, __shfl_xor_sync(0xffffffffu, mx0, 2));
        mx1 = fmaxf(mx1, __shfl_xor_sync(0xffffffffu, mx1, 1));
        mx1 = fmaxf(mx1, __shfl_xor_sync(0xffffffffu, mx1, 2));
        const float mn0 = fmaxf(m0, mx0), mn1 = fmaxf(m1, mx1);
        const float sc0 = __expf(m0 - mn0), sc1 = __expf(m1 - mn1);
        m0 = mn0; m1 = mn1;

        uint32_t ph[4][4];
        float s0 = 0.f, s1 = 0.f;
        #pragma unroll
        for (int nt = 0; nt < 8; nt++) {
            const float p0 = __expf(sacc[nt][0] - mn0);
            const float p1 = __expf(sacc[nt][1] - mn0);
            const float p2 = __expf(sacc[nt][2] - mn1);
            const float p3 = __expf(sacc[nt][3] - mn1);
            s0 += p0 + p1; s1 += p2 + p3;
            const int ks2 = nt >> 1, hf = (nt & 1) * 2;
            ph[ks2][hf]     = packh2(p0, p1);
            ph[ks2][hf + 1] = packh2(p2, p3);
        }
        s0 += __shfl_xor_sync(0xffffffffu, s0, 1);
        s0 += __shfl_xor_sync(0xffffffffu, s0, 2);
        s1 += __shfl_xor_sync(0xffffffffu, s1, 1);
        s1 += __shfl_xor_sync(0xffffffffu, s1, 2);
        l0 = l0 * sc0 + s0;
        l1 = l1 * sc1 + s1;

        #pragma unroll
        for (int dt = 0; dt < 8; dt++) {
            oacc[dt][0] *= sc0; oacc[dt][1] *= sc0;
            oacc[dt][2] *= sc1; oacc[dt][3] *= sc1;
        }

        // ---- O += P V (V via trans ldmatrix) ----
        const uint32_t vtb = stb + ATILE * 2;
        #pragma unroll
        for (int ks = 0; ks < 4; ks++) {
            #pragma unroll
            for (int dp = 0; dp < 4; dp++) {
                const int krow = 16 * ks + (lane & 15);
                const int ncol = dp * 16 + (lane >> 4) * 8;
                uint32_t rv[4];
                ldm_x4_t(rv, vtb + (uint32_t)((krow * APAD + ncol) * 2));
                uint32_t v0[2] = {rv[0], rv[1]}, v1[2] = {rv[2], rv[3]};
                mma16816(oacc[dp * 2],     ph[ks], v0);
                mma16816(oacc[dp * 2 + 1], ph[ks], v1);
            }
        }
        __syncthreads();
    }

    // ---- epilogue: normalize, write ctx (fp16) ----
    const float inv0 = 1.f / l0, inv1 = 1.f / l1;
    const size_t rg0 = (size_t)(b * Tt + qrow0 + wq0 + r0);
    #pragma unroll
    for (int dt = 0; dt < 8; dt++) {
        const int col = colb + dt * 8 + c0;
        {
            const __half2 hp = __floats2half2_rn(oacc[dt][0] * inv0, oacc[dt][1] * inv0);
            *(__half2*)(ch + rg0 * Dd + col) = hp;
        }
        {
            const __half2 hp = __floats2half2_rn(oacc[dt][2] * inv1, oacc[dt][3] * inv1);
            *(__half2*)(ch + (rg0 + 8) * Dd + col) = hp;
        }
    }
}

// ---------------------------------------------------------------------------
// Launch
// ---------------------------------------------------------------------------
extern "C" void kernel_launch(void* const* d_in, const int* in_sizes, int n_in,
                              void* d_out, int out_size)
{
    const float* x    = (const float*)d_in[0];
    const float* ln1s = (const float*)d_in[1];
    const float* ln1b = (const float*)d_in[2];
    const float* wq   = (const float*)d_in[3];
    const float* wk   = (const float*)d_in[4];
    const float* wv   = (const float*)d_in[5];
    const float* wo   = (const float*)d_in[6];
    const float* bo   = (const float*)d_in[7];
    const float* ln2s = (const float*)d_in[8];
    const float* ln2b = (const float*)d_in[9];
    const float* w1   = (const float*)d_in[10];
    const float* b1   = (const float*)d_in[11];
    const float* w2   = (const float*)d_in[12];
    const float* b2   = (const float*)d_in[13];
    float* out = (float*)d_out;

    float* x1;
    cudaGetSymbolAddress((void**)&x1, g_x1);

    __half *xn, *qkv, *ctx, *hbuf, *wqkv, *woh, *w1h, *w2h;
    cudaGetSymbolAddress((void**)&xn,   g_xn);
    cudaGetSymbolAddress((void**)&qkv,  g_qkv);
    cudaGetSymbolAddress((void**)&ctx,  g_ctx);
    cudaGetSymbolAddress((void**)&hbuf, g_h);
    cudaGetSymbolAddress((void**)&wqkv, g_wqkv);
    cudaGetSymbolAddress((void**)&woh,  g_wo);
    cudaGetSymbolAddress((void**)&w1h,  g_w1);
    cudaGetSymbolAddress((void**)&w2h,  g_w2);

    cudaFuncSetAttribute(attn_mma,
                         cudaFuncAttributeMaxDynamicSharedMemorySize, ATTN_SMEM2);
    cudaFuncSetAttribute(gemm_f16<1>,
                         cudaFuncAttributeMaxDynamicSharedMemorySize, PSMEM_BYTES);
    cudaFuncSetAttribute(gemm_f16<2>,
                         cudaFuncAttributeMaxDynamicSharedMemorySize, PSMEM_BYTES);
    cudaFuncSetAttribute(gemm_f16<3>,
                         cudaFuncAttributeMaxDynamicSharedMemorySize, PSMEM_BYTES);

    // All weight conversions in one launch
    cvt_weights<<<(CVT_TOTAL + 255) / 256, 256>>>(
        wq, wk, wv, wo, w1, w2, wqkv, woh, w1h, w2h);

    // LN1 -> xn (fp16)
    ln_f16<<<MROWS, 256>>>(x, ln1s, ln1b, xn);

    // Fused QKV projection -> qkv (fp16), N = 2304
    dim3 gqkv(QKV3 / 128, MROWS / 128);
    gemm_f16<1><<<gqkv, 256, PSMEM_BYTES>>>(xn, wqkv, nullptr, nullptr,
                                            nullptr, qkv, MROWS, QKV3, Dd);

    // Attention (HMMA flash, 128-row q-tiles) -> ctx (fp16)
    dim3 ga(Tt / 128, Hh, Bb);
    attn_mma<<<ga, 256, ATTN_SMEM2>>>(qkv, ctx);

    // O projection + bias + residual -> x1 (fp32)
    dim3 gdd(Dd / 128, MROWS / 128);
    gemm_f16<2><<<gdd, 256, PSMEM_BYTES>>>(ctx, woh, bo, x,
                                           x1, nullptr, MROWS, Dd, Dd);

    // LN2 -> xn (fp16)
    ln_f16<<<MROWS, 256>>>(x1, ln2s, ln2b, xn);

    // MLP1: bias + GELU -> h (fp16)
    dim3 g1(DFF / 128, MROWS / 128);
    gemm_f16<3><<<g1, 256, PSMEM_BYTES>>>(xn, w1h, b1, nullptr,
                                          nullptr, hbuf, MROWS, DFF, Dd);

    // MLP2: bias + residual -> out (fp32)
    gemm_f16<2><<<gdd, 256, PSMEM_BYTES>>>(hbuf, w2h, b2, x1,
                                           out, nullptr, MROWS, Dd, DFF);
}